// round 1
// baseline (speedup 1.0000x reference)
#include <cuda_runtime.h>
#include <math.h>

#define S_LEN 4096
#define D_MODEL 320
#define NH 8
#define DH 40

// -------- scratch (device globals: allocation-free) --------
__device__ float g_q[S_LEN * D_MODEL];
__device__ float g_k[S_LEN * D_MODEL];
__device__ float g_v[S_LEN * D_MODEL];
__device__ float g_ctx[S_LEN * D_MODEL];

// ============================================================
// GEMM: C = A @ W^T   (A[M,K] row-major, W[N,K] row-major)
// BM=BN=64, BK=32, 256 threads, 4x4 register tile per thread.
// ============================================================
__global__ void __launch_bounds__(256) gemm_qkv_kernel(
    const float* __restrict__ x,
    const float* __restrict__ Wq,
    const float* __restrict__ Wk,
    const float* __restrict__ Wv)
{
    const float* __restrict__ W = (blockIdx.z == 0) ? Wq : ((blockIdx.z == 1) ? Wk : Wv);
    float* __restrict__ C = (blockIdx.z == 0) ? g_q : ((blockIdx.z == 1) ? g_k : g_v);

    __shared__ float As[64][33];
    __shared__ float Bs[64][33];

    const int tid = threadIdx.x;
    const int tx = tid & 15;
    const int ty = tid >> 4;
    const int m0 = blockIdx.x * 64;
    const int n0 = blockIdx.y * 64;

    float acc[4][4] = {};

    for (int kb = 0; kb < D_MODEL; kb += 32) {
        #pragma unroll
        for (int it = 0; it < 8; it++) {
            int idx = tid + it * 256;        // 0..2047
            int r = idx >> 5;                // /32
            int c = idx & 31;
            As[r][c] = x[(m0 + r) * D_MODEL + kb + c];
            Bs[r][c] = W[(n0 + r) * D_MODEL + kb + c];
        }
        __syncthreads();

        #pragma unroll
        for (int kk = 0; kk < 32; kk++) {
            float a[4], b[4];
            #pragma unroll
            for (int i = 0; i < 4; i++) a[i] = As[4 * ty + i][kk];
            #pragma unroll
            for (int j = 0; j < 4; j++) b[j] = Bs[4 * tx + j][kk];
            #pragma unroll
            for (int i = 0; i < 4; i++)
                #pragma unroll
                for (int j = 0; j < 4; j++)
                    acc[i][j] = fmaf(a[i], b[j], acc[i][j]);
        }
        __syncthreads();
    }

    #pragma unroll
    for (int i = 0; i < 4; i++)
        #pragma unroll
        for (int j = 0; j < 4; j++)
            C[(m0 + 4 * ty + i) * D_MODEL + n0 + 4 * tx + j] = acc[i][j];
}

// ============================================================
// GEMM with bias: out = g_ctx @ Wo^T + bo
// ============================================================
__global__ void __launch_bounds__(256) gemm_out_kernel(
    const float* __restrict__ Wo,
    const float* __restrict__ bo,
    float* __restrict__ out)
{
    __shared__ float As[64][33];
    __shared__ float Bs[64][33];

    const int tid = threadIdx.x;
    const int tx = tid & 15;
    const int ty = tid >> 4;
    const int m0 = blockIdx.x * 64;
    const int n0 = blockIdx.y * 64;

    float acc[4][4] = {};

    for (int kb = 0; kb < D_MODEL; kb += 32) {
        #pragma unroll
        for (int it = 0; it < 8; it++) {
            int idx = tid + it * 256;
            int r = idx >> 5;
            int c = idx & 31;
            As[r][c] = g_ctx[(m0 + r) * D_MODEL + kb + c];
            Bs[r][c] = Wo[(n0 + r) * D_MODEL + kb + c];
        }
        __syncthreads();

        #pragma unroll
        for (int kk = 0; kk < 32; kk++) {
            float a[4], b[4];
            #pragma unroll
            for (int i = 0; i < 4; i++) a[i] = As[4 * ty + i][kk];
            #pragma unroll
            for (int j = 0; j < 4; j++) b[j] = Bs[4 * tx + j][kk];
            #pragma unroll
            for (int i = 0; i < 4; i++)
                #pragma unroll
                for (int j = 0; j < 4; j++)
                    acc[i][j] = fmaf(a[i], b[j], acc[i][j]);
        }
        __syncthreads();
    }

    #pragma unroll
    for (int i = 0; i < 4; i++) {
        #pragma unroll
        for (int j = 0; j < 4; j++) {
            int n = n0 + 4 * tx + j;
            out[(m0 + 4 * ty + i) * D_MODEL + n] = acc[i][j] + bo[n];
        }
    }
}

// ============================================================
// Flash attention (fp32): one CTA = 64 query rows x 1 head.
// Streams 64-key blocks: S = Q K^T, online softmax, O += P V.
// DH padded to 48 for the AV epilogue tiling (cols = tx + 16*jj).
// ============================================================
#define DHP 48   // padded head dim for V/O tiling
// smem: Qs[64][41] + Ks[64][41] + Vs[64][48] + Ps[64][65]
#define ATTN_SMEM_FLOATS (2 * 64 * 41 + 64 * 48 + 64 * 65)
#define ATTN_SMEM_BYTES  (ATTN_SMEM_FLOATS * 4)

__global__ void __launch_bounds__(256) attn_kernel()
{
    extern __shared__ float sm[];
    float (*Qs)[41] = (float (*)[41])(sm);
    float (*Ks)[41] = (float (*)[41])(sm + 64 * 41);
    float (*Vs)[48] = (float (*)[48])(sm + 2 * 64 * 41);
    float (*Ps)[65] = (float (*)[65])(sm + 2 * 64 * 41 + 64 * 48);

    const int tid = threadIdx.x;
    const int tx = tid & 15;
    const int ty = tid >> 4;
    const int head = blockIdx.y;
    const int q0 = blockIdx.x * 64;
    const float scale = rsqrtf((float)DH);

    // Load Q tile (pre-scaled)
    for (int idx = tid; idx < 64 * DH; idx += 256) {
        int r = idx / DH;
        int c = idx % DH;
        Qs[r][c] = g_q[(q0 + r) * D_MODEL + head * DH + c] * scale;
    }

    float m[4], l[4], o[4][3];
    #pragma unroll
    for (int i = 0; i < 4; i++) {
        m[i] = -1e30f;
        l[i] = 0.f;
        #pragma unroll
        for (int jj = 0; jj < 3; jj++) o[i][jj] = 0.f;
    }

    for (int kb = 0; kb < S_LEN; kb += 64) {
        // protects: prior-iter AV readers of Ks/Vs/Ps, and Q-load on iter 0
        __syncthreads();

        for (int idx = tid; idx < 64 * DH; idx += 256) {
            int r = idx / DH;
            int c = idx % DH;
            Ks[r][c] = g_k[(kb + r) * D_MODEL + head * DH + c];
        }
        for (int idx = tid; idx < 64 * DHP; idx += 256) {
            int r = idx / DHP;
            int c = idx % DHP;
            Vs[r][c] = (c < DH) ? g_v[(kb + r) * D_MODEL + head * DH + c] : 0.f;
        }
        __syncthreads();

        // S = Q K^T (pre-scaled)
        float s[4][4] = {};
        #pragma unroll 8
        for (int k = 0; k < DH; k++) {
            float a[4], b[4];
            #pragma unroll
            for (int i = 0; i < 4; i++) a[i] = Qs[4 * ty + i][k];
            #pragma unroll
            for (int j = 0; j < 4; j++) b[j] = Ks[4 * tx + j][k];
            #pragma unroll
            for (int i = 0; i < 4; i++)
                #pragma unroll
                for (int j = 0; j < 4; j++)
                    s[i][j] = fmaf(a[i], b[j], s[i][j]);
        }

        // online softmax (row reductions across the 16 tx lanes)
        #pragma unroll
        for (int i = 0; i < 4; i++) {
            float rm = fmaxf(fmaxf(s[i][0], s[i][1]), fmaxf(s[i][2], s[i][3]));
            #pragma unroll
            for (int off = 8; off > 0; off >>= 1)
                rm = fmaxf(rm, __shfl_xor_sync(0xffffffffu, rm, off));
            float mn = fmaxf(m[i], rm);
            float corr = __expf(m[i] - mn);
            m[i] = mn;
            float rs = 0.f;
            #pragma unroll
            for (int j = 0; j < 4; j++) {
                s[i][j] = __expf(s[i][j] - mn);
                rs += s[i][j];
            }
            #pragma unroll
            for (int off = 8; off > 0; off >>= 1)
                rs += __shfl_xor_sync(0xffffffffu, rs, off);
            l[i] = l[i] * corr + rs;
            #pragma unroll
            for (int jj = 0; jj < 3; jj++) o[i][jj] *= corr;
            #pragma unroll
            for (int j = 0; j < 4; j++)
                Ps[4 * ty + i][4 * tx + j] = s[i][j];
        }
        __syncthreads();

        // O += P @ V
        #pragma unroll 4
        for (int jk = 0; jk < 64; jk++) {
            float p[4], v[3];
            #pragma unroll
            for (int i = 0; i < 4; i++) p[i] = Ps[4 * ty + i][jk];
            #pragma unroll
            for (int jj = 0; jj < 3; jj++) v[jj] = Vs[jk][tx + 16 * jj];
            #pragma unroll
            for (int i = 0; i < 4; i++)
                #pragma unroll
                for (int jj = 0; jj < 3; jj++)
                    o[i][jj] = fmaf(p[i], v[jj], o[i][jj]);
        }
    }

    // epilogue: O / l -> merged-head ctx layout [S, H*DH]
    #pragma unroll
    for (int i = 0; i < 4; i++) {
        float inv = 1.f / l[i];
        #pragma unroll
        for (int jj = 0; jj < 3; jj++) {
            int c = tx + 16 * jj;
            if (c < DH)
                g_ctx[(q0 + 4 * ty + i) * D_MODEL + head * DH + c] = o[i][jj] * inv;
        }
    }
}

// ============================================================
extern "C" void kernel_launch(void* const* d_in, const int* in_sizes, int n_in,
                              void* d_out, int out_size)
{
    const float* x  = (const float*)d_in[0];
    const float* Wq = (const float*)d_in[1];
    const float* Wk = (const float*)d_in[2];
    const float* Wv = (const float*)d_in[3];
    const float* Wo = (const float*)d_in[4];
    const float* bo = (const float*)d_in[5];
    float* out = (float*)d_out;

    cudaFuncSetAttribute(attn_kernel,
                         cudaFuncAttributeMaxDynamicSharedMemorySize,
                         ATTN_SMEM_BYTES);

    // 1) Q,K,V projections: y = x @ W^T  (z selects matrix)
    gemm_qkv_kernel<<<dim3(S_LEN / 64, D_MODEL / 64, 3), 256>>>(x, Wq, Wk, Wv);

    // 2) flash attention per (q-block, head)
    attn_kernel<<<dim3(S_LEN / 64, NH), 256, ATTN_SMEM_BYTES>>>();

    // 3) output projection + bias
    gemm_out_kernel<<<dim3(S_LEN / 64, D_MODEL / 64), 256>>>(Wo, bo, out);
}

// round 3
// speedup vs baseline: 2.2152x; 2.2152x over previous
#include <cuda_runtime.h>
#include <cuda_fp16.h>
#include <stdint.h>
#include <math.h>

#define S_LEN 4096
#define D_MODEL 320
#define NH 8
#define DH 40
#define BR 128
#define BC 64

// -------- scratch (device globals: allocation-free) --------
__device__ float g_q[S_LEN * D_MODEL];
__device__ float g_k[S_LEN * D_MODEL];
__device__ float g_v[S_LEN * D_MODEL];
__device__ float g_ctx[S_LEN * D_MODEL];

// ============================================================
// fp32 SIMT GEMM: C = A @ W^T  (kept fp32 for accuracy budget)
// ============================================================
__global__ void __launch_bounds__(256) gemm_qkv_kernel(
    const float* __restrict__ x,
    const float* __restrict__ Wq,
    const float* __restrict__ Wk,
    const float* __restrict__ Wv)
{
    const float* __restrict__ W = (blockIdx.z == 0) ? Wq : ((blockIdx.z == 1) ? Wk : Wv);
    float* __restrict__ C = (blockIdx.z == 0) ? g_q : ((blockIdx.z == 1) ? g_k : g_v);

    __shared__ float As[64][33];
    __shared__ float Bs[64][33];

    const int tid = threadIdx.x;
    const int tx = tid & 15;
    const int ty = tid >> 4;
    const int m0 = blockIdx.x * 64;
    const int n0 = blockIdx.y * 64;

    float acc[4][4] = {};

    for (int kb = 0; kb < D_MODEL; kb += 32) {
        #pragma unroll
        for (int it = 0; it < 8; it++) {
            int idx = tid + it * 256;
            int r = idx >> 5;
            int c = idx & 31;
            As[r][c] = x[(m0 + r) * D_MODEL + kb + c];
            Bs[r][c] = W[(n0 + r) * D_MODEL + kb + c];
        }
        __syncthreads();

        #pragma unroll
        for (int kk = 0; kk < 32; kk++) {
            float a[4], b[4];
            #pragma unroll
            for (int i = 0; i < 4; i++) a[i] = As[4 * ty + i][kk];
            #pragma unroll
            for (int j = 0; j < 4; j++) b[j] = Bs[4 * tx + j][kk];
            #pragma unroll
            for (int i = 0; i < 4; i++)
                #pragma unroll
                for (int j = 0; j < 4; j++)
                    acc[i][j] = fmaf(a[i], b[j], acc[i][j]);
        }
        __syncthreads();
    }

    #pragma unroll
    for (int i = 0; i < 4; i++)
        #pragma unroll
        for (int j = 0; j < 4; j++)
            C[(m0 + 4 * ty + i) * D_MODEL + n0 + 4 * tx + j] = acc[i][j];
}

__global__ void __launch_bounds__(256) gemm_out_kernel(
    const float* __restrict__ Wo,
    const float* __restrict__ bo,
    float* __restrict__ out)
{
    __shared__ float As[64][33];
    __shared__ float Bs[64][33];

    const int tid = threadIdx.x;
    const int tx = tid & 15;
    const int ty = tid >> 4;
    const int m0 = blockIdx.x * 64;
    const int n0 = blockIdx.y * 64;

    float acc[4][4] = {};

    for (int kb = 0; kb < D_MODEL; kb += 32) {
        #pragma unroll
        for (int it = 0; it < 8; it++) {
            int idx = tid + it * 256;
            int r = idx >> 5;
            int c = idx & 31;
            As[r][c] = g_ctx[(m0 + r) * D_MODEL + kb + c];
            Bs[r][c] = Wo[(n0 + r) * D_MODEL + kb + c];
        }
        __syncthreads();

        #pragma unroll
        for (int kk = 0; kk < 32; kk++) {
            float a[4], b[4];
            #pragma unroll
            for (int i = 0; i < 4; i++) a[i] = As[4 * ty + i][kk];
            #pragma unroll
            for (int j = 0; j < 4; j++) b[j] = Bs[4 * tx + j][kk];
            #pragma unroll
            for (int i = 0; i < 4; i++)
                #pragma unroll
                for (int j = 0; j < 4; j++)
                    acc[i][j] = fmaf(a[i], b[j], acc[i][j]);
        }
        __syncthreads();
    }

    #pragma unroll
    for (int i = 0; i < 4; i++) {
        #pragma unroll
        for (int j = 0; j < 4; j++) {
            int n = n0 + 4 * tx + j;
            out[(m0 + 4 * ty + i) * D_MODEL + n] = acc[i][j] + bo[n];
        }
    }
}

// ============================================================
// Flash attention with HMMA (mma.sync m16n8k16 f16, fp32 acc).
// CTA = 128 queries x 1 head. 8 warps, each owns m16 x n64 tile.
// DH=40 padded to 48 (3 x k16) for QK; PV: k=64 keys, n=40 (5 atoms).
// ============================================================

__device__ __forceinline__ void mma_f16(float c[4], uint32_t a0, uint32_t a1,
                                        uint32_t a2, uint32_t a3,
                                        uint32_t b0, uint32_t b1)
{
    asm volatile(
        "mma.sync.aligned.m16n8k16.row.col.f32.f16.f16.f32 "
        "{%0,%1,%2,%3}, {%4,%5,%6,%7}, {%8,%9}, {%0,%1,%2,%3};\n"
        : "+f"(c[0]), "+f"(c[1]), "+f"(c[2]), "+f"(c[3])
        : "r"(a0), "r"(a1), "r"(a2), "r"(a3), "r"(b0), "r"(b1));
}

// smem strides (in uint32/half2 units) chosen conflict-free for
// fragment access pattern (row = lane/4 based, col = lane%4 based):
//   stride 28: bank = (28g + t) % 32 = (-4g + t) -> 32 distinct
//   stride 36: bank = (36g + t) % 32 = ( 4g + t) -> 32 distinct
#define QS_STRIDE 28
#define KS_STRIDE 28
#define VT_STRIDE 36
#define PS_STRIDE 36

__global__ void __launch_bounds__(256) attn_kernel()
{
    __shared__ uint32_t Qs[128 * QS_STRIDE];  // 128 x 24 half2 (48 halves, cols>=40 zero)
    __shared__ uint32_t Ks[64 * KS_STRIDE];   // 64 x 24 half2
    __shared__ uint32_t Vt[40 * VT_STRIDE];   // transposed: [dh][32 half2 over 64 keys]
    __shared__ uint32_t Ps[128 * PS_STRIDE];  // per-warp 16-row bands, 32 half2 cols

    const int tid = threadIdx.x;
    const int w = tid >> 5;
    const int lane = tid & 31;
    const int g = lane >> 2;   // groupID   (fragment row selector)
    const int t = lane & 3;    // tid-in-group (fragment col selector)
    const int head = blockIdx.y;
    const int q0 = blockIdx.x * BR;
    const float scale = rsqrtf((float)DH);

    // ---- load Q tile (pre-scaled, fp16, zero-padded to 48 cols) ----
    for (int idx = tid; idx < 128 * 24; idx += 256) {
        int r = idx / 24, h = idx % 24;
        int c = 2 * h;
        float f0 = 0.f, f1 = 0.f;
        if (c < DH) {
            const float* p = &g_q[(q0 + r) * D_MODEL + head * DH + c];
            f0 = p[0] * scale;
            f1 = p[1] * scale;
        }
        __half2 hv = __floats2half2_rn(f0, f1);
        Qs[r * QS_STRIDE + h] = *(uint32_t*)&hv;
    }
    __syncthreads();

    // ---- Q A-fragments register-resident: 3 k-steps ----
    uint32_t qa[3][4];
    {
        int r0 = (w * 16 + g) * QS_STRIDE;
        int r1 = r0 + 8 * QS_STRIDE;
        #pragma unroll
        for (int ks = 0; ks < 3; ks++) {
            qa[ks][0] = Qs[r0 + ks * 8 + t];
            qa[ks][1] = Qs[r1 + ks * 8 + t];
            qa[ks][2] = Qs[r0 + ks * 8 + t + 4];
            qa[ks][3] = Qs[r1 + ks * 8 + t + 4];
        }
    }

    float m0 = -1e30f, m1 = -1e30f;
    float l0 = 0.f, l1 = 0.f;
    float o[5][4] = {};

    for (int kb = 0; kb < S_LEN; kb += BC) {
        __syncthreads();  // prior-iter readers of Ks/Vt done

        // ---- load K tile (fp16, padded) ----
        for (int idx = tid; idx < 64 * 24; idx += 256) {
            int r = idx / 24, h = idx % 24;
            int c = 2 * h;
            float f0 = 0.f, f1 = 0.f;
            if (c < DH) {
                const float* p = &g_k[(kb + r) * D_MODEL + head * DH + c];
                f0 = p[0];
                f1 = p[1];
            }
            __half2 hv = __floats2half2_rn(f0, f1);
            Ks[r * KS_STRIDE + h] = *(uint32_t*)&hv;
        }
        // ---- load V transposed: Vt[d][key-pair] ----
        for (int idx = tid; idx < 40 * 32; idx += 256) {
            int d = idx >> 5;
            int h = idx & 31;
            int k0 = 2 * h;
            float f0 = g_v[(kb + k0) * D_MODEL + head * DH + d];
            float f1 = g_v[(kb + k0 + 1) * D_MODEL + head * DH + d];
            __half2 hv = __floats2half2_rn(f0, f1);
            Vt[d * VT_STRIDE + h] = *(uint32_t*)&hv;
        }
        __syncthreads();

        // ---- S = Q K^T : 8 n-atoms x 4 regs ----
        float s[8][4];
        #pragma unroll
        for (int a = 0; a < 8; a++)
            #pragma unroll
            for (int j = 0; j < 4; j++) s[a][j] = 0.f;

        #pragma unroll
        for (int ks = 0; ks < 3; ks++) {
            #pragma unroll
            for (int a = 0; a < 8; a++) {
                int kr = (a * 8 + g) * KS_STRIDE + ks * 8 + t;
                uint32_t b0 = Ks[kr];
                uint32_t b1 = Ks[kr + 4];
                mma_f16(s[a], qa[ks][0], qa[ks][1], qa[ks][2], qa[ks][3], b0, b1);
            }
        }

        // ---- online softmax (rows r0 = w*16+g, r1 = r0+8) ----
        float rm0 = -1e30f, rm1 = -1e30f;
        #pragma unroll
        for (int a = 0; a < 8; a++) {
            rm0 = fmaxf(rm0, fmaxf(s[a][0], s[a][1]));
            rm1 = fmaxf(rm1, fmaxf(s[a][2], s[a][3]));
        }
        #pragma unroll
        for (int off = 1; off <= 2; off <<= 1) {
            rm0 = fmaxf(rm0, __shfl_xor_sync(0xffffffffu, rm0, off));
            rm1 = fmaxf(rm1, __shfl_xor_sync(0xffffffffu, rm1, off));
        }
        float mn0 = fmaxf(m0, rm0);
        float mn1 = fmaxf(m1, rm1);
        float corr0 = __expf(m0 - mn0);
        float corr1 = __expf(m1 - mn1);
        m0 = mn0; m1 = mn1;

        float rs0 = 0.f, rs1 = 0.f;
        #pragma unroll
        for (int a = 0; a < 8; a++) {
            s[a][0] = __expf(s[a][0] - mn0);
            s[a][1] = __expf(s[a][1] - mn0);
            s[a][2] = __expf(s[a][2] - mn1);
            s[a][3] = __expf(s[a][3] - mn1);
            rs0 += s[a][0] + s[a][1];
            rs1 += s[a][2] + s[a][3];
        }
        #pragma unroll
        for (int off = 1; off <= 2; off <<= 1) {
            rs0 += __shfl_xor_sync(0xffffffffu, rs0, off);
            rs1 += __shfl_xor_sync(0xffffffffu, rs1, off);
        }
        l0 = l0 * corr0 + rs0;
        l1 = l1 * corr1 + rs1;
        #pragma unroll
        for (int n = 0; n < 5; n++) {
            o[n][0] *= corr0; o[n][1] *= corr0;
            o[n][2] *= corr1; o[n][3] *= corr1;
        }

        // ---- store P (fp16) into warp-private band ----
        int pr0 = (w * 16 + g) * PS_STRIDE;
        int pr1 = pr0 + 8 * PS_STRIDE;
        #pragma unroll
        for (int a = 0; a < 8; a++) {
            __half2 h01 = __floats2half2_rn(s[a][0], s[a][1]);
            __half2 h23 = __floats2half2_rn(s[a][2], s[a][3]);
            Ps[pr0 + a * 4 + t] = *(uint32_t*)&h01;
            Ps[pr1 + a * 4 + t] = *(uint32_t*)&h23;
        }
        __syncwarp();

        // ---- O += P @ V : 4 k-steps x 5 n-atoms ----
        #pragma unroll
        for (int ks = 0; ks < 4; ks++) {
            uint32_t pa0 = Ps[pr0 + ks * 8 + t];
            uint32_t pa1 = Ps[pr1 + ks * 8 + t];
            uint32_t pa2 = Ps[pr0 + ks * 8 + t + 4];
            uint32_t pa3 = Ps[pr1 + ks * 8 + t + 4];
            #pragma unroll
            for (int n = 0; n < 5; n++) {
                int vr = (n * 8 + g) * VT_STRIDE + ks * 8 + t;
                uint32_t b0 = Vt[vr];
                uint32_t b1 = Vt[vr + 4];
                mma_f16(o[n], pa0, pa1, pa2, pa3, b0, b1);
            }
        }
        __syncwarp();
    }

    // ---- epilogue: O / l -> merged-head ctx ----
    float inv0 = 1.f / l0;
    float inv1 = 1.f / l1;
    int r0 = q0 + w * 16 + g;
    #pragma unroll
    for (int n = 0; n < 5; n++) {
        int col = head * DH + n * 8 + 2 * t;
        float2 v0 = make_float2(o[n][0] * inv0, o[n][1] * inv0);
        float2 v1 = make_float2(o[n][2] * inv1, o[n][3] * inv1);
        *(float2*)&g_ctx[r0 * D_MODEL + col] = v0;
        *(float2*)&g_ctx[(r0 + 8) * D_MODEL + col] = v1;
    }
}

// ============================================================
extern "C" void kernel_launch(void* const* d_in, const int* in_sizes, int n_in,
                              void* d_out, int out_size)
{
    const float* x  = (const float*)d_in[0];
    const float* Wq = (const float*)d_in[1];
    const float* Wk = (const float*)d_in[2];
    const float* Wv = (const float*)d_in[3];
    const float* Wo = (const float*)d_in[4];
    const float* bo = (const float*)d_in[5];
    float* out = (float*)d_out;

    // 1) Q,K,V projections (fp32)
    gemm_qkv_kernel<<<dim3(S_LEN / 64, D_MODEL / 64, 3), 256>>>(x, Wq, Wk, Wv);

    // 2) flash attention (HMMA fp16, fp32 softmax/accum)
    attn_kernel<<<dim3(S_LEN / BR, NH), 256>>>();

    // 3) output projection + bias (fp32)
    gemm_out_kernel<<<dim3(S_LEN / 64, D_MODEL / 64), 256>>>(Wo, bo, out);
}

// round 4
// speedup vs baseline: 2.8833x; 1.3016x over previous
#include <cuda_runtime.h>
#include <cuda_fp16.h>
#include <stdint.h>
#include <math.h>

#define S_LEN 4096
#define D_MODEL 320
#define DU32 160          // D_MODEL halves as u32
#define NH 8
#define DH 40
#define BR 128
#define BC 64

// -------- scratch (device globals: allocation-free) --------
__device__ __half g_xh[S_LEN * D_MODEL];
__device__ __half g_xl[S_LEN * D_MODEL];
__device__ __half g_wh[4 * D_MODEL * D_MODEL];
__device__ __half g_wl[4 * D_MODEL * D_MODEL];
__device__ __half g_qh[S_LEN * D_MODEL];
__device__ __half g_kh[S_LEN * D_MODEL];
__device__ __half g_vh[S_LEN * D_MODEL];
__device__ __half g_ch[S_LEN * D_MODEL];
__device__ __half g_cl[S_LEN * D_MODEL];

// ============================================================
// conversion kernels: fp32 -> (hi, lo) fp16 split
// ============================================================
__global__ void __launch_bounds__(256) convert_x_kernel(const float* __restrict__ x)
{
    int i = blockIdx.x * 256 + threadIdx.x;
    if (i < S_LEN * D_MODEL) {
        float v = x[i];
        __half h = __float2half_rn(v);
        g_xh[i] = h;
        g_xl[i] = __float2half_rn(v - __half2float(h));
    }
}

__global__ void __launch_bounds__(256) convert_w_kernel(
    const float* __restrict__ Wq, const float* __restrict__ Wk,
    const float* __restrict__ Wv, const float* __restrict__ Wo)
{
    int z = blockIdx.z;
    const float* W = (z == 0) ? Wq : (z == 1) ? Wk : (z == 2) ? Wv : Wo;
    float scale = (z == 0) ? rsqrtf((float)DH) : 1.0f;
    int i = blockIdx.x * 256 + threadIdx.x;
    if (i < D_MODEL * D_MODEL) {
        float v = W[i] * scale;
        __half h = __float2half_rn(v);
        g_wh[z * D_MODEL * D_MODEL + i] = h;
        g_wl[z * D_MODEL * D_MODEL + i] = __float2half_rn(v - __half2float(h));
    }
}

// ============================================================
// HMMA helpers
// ============================================================
__device__ __forceinline__ void mma_f16(float c[4], uint32_t a0, uint32_t a1,
                                        uint32_t a2, uint32_t a3,
                                        uint32_t b0, uint32_t b1)
{
    asm volatile(
        "mma.sync.aligned.m16n8k16.row.col.f32.f16.f16.f32 "
        "{%0,%1,%2,%3}, {%4,%5,%6,%7}, {%8,%9}, {%0,%1,%2,%3};\n"
        : "+f"(c[0]), "+f"(c[1]), "+f"(c[2]), "+f"(c[3])
        : "r"(a0), "r"(a1), "r"(a2), "r"(a3), "r"(b0), "r"(b1));
}

__device__ __forceinline__ void ldmatrix_x2_trans(uint32_t& r0, uint32_t& r1, uint32_t addr)
{
    asm volatile("ldmatrix.sync.aligned.m8n8.x2.trans.shared.b16 {%0,%1}, [%2];"
                 : "=r"(r0), "=r"(r1) : "r"(addr));
}

// ============================================================
// Split-fp16 HMMA GEMM: C = A @ W^T, 3-term compensated.
// BM=128 (8 warps x m16), BN=64, k-step 16. A=x split, W split.
// Writes half output (q/k/v merged-head layout).
// ============================================================
#define PA_STR 12   // u32 stride: banks (12g+t) distinct over lanes

__global__ void __launch_bounds__(256) gemm_qkv_h()
{
    __shared__ __align__(16) uint32_t Ah[128 * PA_STR];
    __shared__ __align__(16) uint32_t Al[128 * PA_STR];
    __shared__ __align__(16) uint32_t Wh[64 * PA_STR];
    __shared__ __align__(16) uint32_t Wl[64 * PA_STR];

    const int z = blockIdx.z;
    const uint32_t* __restrict__ xh32 = (const uint32_t*)g_xh;
    const uint32_t* __restrict__ xl32 = (const uint32_t*)g_xl;
    const uint32_t* __restrict__ wh32 = (const uint32_t*)(g_wh + z * D_MODEL * D_MODEL);
    const uint32_t* __restrict__ wl32 = (const uint32_t*)(g_wl + z * D_MODEL * D_MODEL);
    uint32_t* __restrict__ out32 =
        (uint32_t*)((z == 0) ? g_qh : (z == 1) ? g_kh : g_vh);

    const int tid = threadIdx.x;
    const int w = tid >> 5;
    const int lane = tid & 31;
    const int g = lane >> 2;
    const int t = lane & 3;
    const int m0 = blockIdx.x * 128;
    const int n0 = blockIdx.y * 64;

    float acc[8][4] = {};

    for (int kb = 0; kb < 20; kb++) {       // 20 k-steps of 16
        __syncthreads();
        #pragma unroll
        for (int it = 0; it < 4; it++) {    // A tiles: 1024 u32 each
            int idx = tid + it * 256;
            int r = idx >> 3, c = idx & 7;
            Ah[r * PA_STR + c] = xh32[(m0 + r) * DU32 + kb * 8 + c];
            Al[r * PA_STR + c] = xl32[(m0 + r) * DU32 + kb * 8 + c];
        }
        #pragma unroll
        for (int it = 0; it < 2; it++) {    // W tiles: 512 u32 each
            int idx = tid + it * 256;
            int r = idx >> 3, c = idx & 7;
            Wh[r * PA_STR + c] = wh32[(n0 + r) * DU32 + kb * 8 + c];
            Wl[r * PA_STR + c] = wl32[(n0 + r) * DU32 + kb * 8 + c];
        }
        __syncthreads();

        int r0 = (w * 16 + g) * PA_STR;
        int r1 = r0 + 8 * PA_STR;
        uint32_t ah0 = Ah[r0 + t], ah1 = Ah[r1 + t], ah2 = Ah[r0 + t + 4], ah3 = Ah[r1 + t + 4];
        uint32_t al0 = Al[r0 + t], al1 = Al[r1 + t], al2 = Al[r0 + t + 4], al3 = Al[r1 + t + 4];

        #pragma unroll
        for (int a = 0; a < 8; a++) {
            int br = (a * 8 + g) * PA_STR;
            uint32_t bh0 = Wh[br + t], bh1 = Wh[br + t + 4];
            uint32_t bl0 = Wl[br + t], bl1 = Wl[br + t + 4];
            mma_f16(acc[a], ah0, ah1, ah2, ah3, bh0, bh1);
            mma_f16(acc[a], al0, al1, al2, al3, bh0, bh1);
            mma_f16(acc[a], ah0, ah1, ah2, ah3, bl0, bl1);
        }
    }

    int row = m0 + w * 16 + g;
    #pragma unroll
    for (int a = 0; a < 8; a++) {
        int colu = (n0 >> 1) + 4 * a + t;   // u32 col
        __half2 v0 = __floats2half2_rn(acc[a][0], acc[a][1]);
        __half2 v1 = __floats2half2_rn(acc[a][2], acc[a][3]);
        out32[row * DU32 + colu] = *(uint32_t*)&v0;
        out32[(row + 8) * DU32 + colu] = *(uint32_t*)&v1;
    }
}

// ============================================================
// Output projection: out = ctx @ Wo^T + bo (fp32 output)
// ============================================================
__global__ void __launch_bounds__(256) gemm_out_h(
    const float* __restrict__ bo, float* __restrict__ out)
{
    __shared__ __align__(16) uint32_t Ah[128 * PA_STR];
    __shared__ __align__(16) uint32_t Al[128 * PA_STR];
    __shared__ __align__(16) uint32_t Wh[64 * PA_STR];
    __shared__ __align__(16) uint32_t Wl[64 * PA_STR];

    const uint32_t* __restrict__ xh32 = (const uint32_t*)g_ch;
    const uint32_t* __restrict__ xl32 = (const uint32_t*)g_cl;
    const uint32_t* __restrict__ wh32 = (const uint32_t*)(g_wh + 3 * D_MODEL * D_MODEL);
    const uint32_t* __restrict__ wl32 = (const uint32_t*)(g_wl + 3 * D_MODEL * D_MODEL);

    const int tid = threadIdx.x;
    const int w = tid >> 5;
    const int lane = tid & 31;
    const int g = lane >> 2;
    const int t = lane & 3;
    const int m0 = blockIdx.x * 128;
    const int n0 = blockIdx.y * 64;

    float acc[8][4] = {};

    for (int kb = 0; kb < 20; kb++) {
        __syncthreads();
        #pragma unroll
        for (int it = 0; it < 4; it++) {
            int idx = tid + it * 256;
            int r = idx >> 3, c = idx & 7;
            Ah[r * PA_STR + c] = xh32[(m0 + r) * DU32 + kb * 8 + c];
            Al[r * PA_STR + c] = xl32[(m0 + r) * DU32 + kb * 8 + c];
        }
        #pragma unroll
        for (int it = 0; it < 2; it++) {
            int idx = tid + it * 256;
            int r = idx >> 3, c = idx & 7;
            Wh[r * PA_STR + c] = wh32[(n0 + r) * DU32 + kb * 8 + c];
            Wl[r * PA_STR + c] = wl32[(n0 + r) * DU32 + kb * 8 + c];
        }
        __syncthreads();

        int r0 = (w * 16 + g) * PA_STR;
        int r1 = r0 + 8 * PA_STR;
        uint32_t ah0 = Ah[r0 + t], ah1 = Ah[r1 + t], ah2 = Ah[r0 + t + 4], ah3 = Ah[r1 + t + 4];
        uint32_t al0 = Al[r0 + t], al1 = Al[r1 + t], al2 = Al[r0 + t + 4], al3 = Al[r1 + t + 4];

        #pragma unroll
        for (int a = 0; a < 8; a++) {
            int br = (a * 8 + g) * PA_STR;
            uint32_t bh0 = Wh[br + t], bh1 = Wh[br + t + 4];
            uint32_t bl0 = Wl[br + t], bl1 = Wl[br + t + 4];
            mma_f16(acc[a], ah0, ah1, ah2, ah3, bh0, bh1);
            mma_f16(acc[a], al0, al1, al2, al3, bh0, bh1);
            mma_f16(acc[a], ah0, ah1, ah2, ah3, bl0, bl1);
        }
    }

    int row = m0 + w * 16 + g;
    #pragma unroll
    for (int a = 0; a < 8; a++) {
        int col = n0 + 8 * a + 2 * t;
        float b0v = bo[col], b1v = bo[col + 1];
        float2 v0 = make_float2(acc[a][0] + b0v, acc[a][1] + b1v);
        float2 v1 = make_float2(acc[a][2] + b0v, acc[a][3] + b1v);
        *(float2*)&out[row * D_MODEL + col] = v0;
        *(float2*)&out[(row + 8) * D_MODEL + col] = v1;
    }
}

// ============================================================
// Flash attention (HMMA). CTA = 128 q x 1 head, 8 warps.
// Q/K/V read as fp16. V loaded row-major coalesced; PV B-frags
// via ldmatrix.x2.trans (stride 28 -> conflict-free).
// ============================================================
#define QS_STRIDE 28
#define KS_STRIDE 28
#define VS_STRIDE 28
#define PS_STRIDE 36

__global__ void __launch_bounds__(256) attn_kernel()
{
    __shared__ __align__(16) uint32_t Qs[128 * QS_STRIDE];
    __shared__ __align__(16) uint32_t Ks[64 * KS_STRIDE];
    __shared__ __align__(16) uint32_t Vs[64 * VS_STRIDE];
    __shared__ __align__(16) uint32_t Ps[128 * PS_STRIDE];

    const uint32_t* __restrict__ q32 = (const uint32_t*)g_qh;
    const uint32_t* __restrict__ k32 = (const uint32_t*)g_kh;
    const uint32_t* __restrict__ v32 = (const uint32_t*)g_vh;

    const int tid = threadIdx.x;
    const int w = tid >> 5;
    const int lane = tid & 31;
    const int g = lane >> 2;
    const int t = lane & 3;
    const int head = blockIdx.y;
    const int q0 = blockIdx.x * BR;
    const int hoff = head * (DH / 2);   // u32 col offset of this head

    // ---- load Q tile: 128 rows x 24 u32 (20 data + 4 zero) ----
    for (int idx = tid; idx < 128 * 24; idx += 256) {
        int r = idx / 24, c = idx % 24;
        Qs[r * QS_STRIDE + c] = (c < 20) ? q32[(q0 + r) * DU32 + hoff + c] : 0u;
    }
    __syncthreads();

    // ---- Q A-fragments register-resident ----
    uint32_t qa[3][4];
    {
        int r0 = (w * 16 + g) * QS_STRIDE;
        int r1 = r0 + 8 * QS_STRIDE;
        #pragma unroll
        for (int ks = 0; ks < 3; ks++) {
            qa[ks][0] = Qs[r0 + ks * 8 + t];
            qa[ks][1] = Qs[r1 + ks * 8 + t];
            qa[ks][2] = Qs[r0 + ks * 8 + t + 4];
            qa[ks][3] = Qs[r1 + ks * 8 + t + 4];
        }
    }

    uint32_t vs_shared = (uint32_t)__cvta_generic_to_shared(&Vs[0]);
    uint32_t vrow = vs_shared + (lane & 15) * (VS_STRIDE * 4);

    float m0 = -1e30f, m1 = -1e30f;
    float l0 = 0.f, l1 = 0.f;
    float o[5][4] = {};

    for (int kb = 0; kb < S_LEN; kb += BC) {
        __syncthreads();

        // ---- K tile: 64 x 24 u32 (zero-padded cols 20..23) ----
        for (int idx = tid; idx < 64 * 24; idx += 256) {
            int r = idx / 24, c = idx % 24;
            Ks[r * KS_STRIDE + c] = (c < 20) ? k32[(kb + r) * DU32 + hoff + c] : 0u;
        }
        // ---- V tile: 64 x 20 u32, row-major, coalesced ----
        for (int idx = tid; idx < 64 * 20; idx += 256) {
            int r = idx / 20, c = idx % 20;
            Vs[r * VS_STRIDE + c] = v32[(kb + r) * DU32 + hoff + c];
        }
        __syncthreads();

        // ---- S = Q K^T ----
        float s[8][4];
        #pragma unroll
        for (int a = 0; a < 8; a++)
            #pragma unroll
            for (int j = 0; j < 4; j++) s[a][j] = 0.f;

        #pragma unroll
        for (int ks = 0; ks < 3; ks++) {
            #pragma unroll
            for (int a = 0; a < 8; a++) {
                int kr = (a * 8 + g) * KS_STRIDE + ks * 8 + t;
                mma_f16(s[a], qa[ks][0], qa[ks][1], qa[ks][2], qa[ks][3],
                        Ks[kr], Ks[kr + 4]);
            }
        }

        // ---- online softmax ----
        float rm0 = -1e30f, rm1 = -1e30f;
        #pragma unroll
        for (int a = 0; a < 8; a++) {
            rm0 = fmaxf(rm0, fmaxf(s[a][0], s[a][1]));
            rm1 = fmaxf(rm1, fmaxf(s[a][2], s[a][3]));
        }
        #pragma unroll
        for (int off = 1; off <= 2; off <<= 1) {
            rm0 = fmaxf(rm0, __shfl_xor_sync(0xffffffffu, rm0, off));
            rm1 = fmaxf(rm1, __shfl_xor_sync(0xffffffffu, rm1, off));
        }
        float mn0 = fmaxf(m0, rm0);
        float mn1 = fmaxf(m1, rm1);
        float corr0 = __expf(m0 - mn0);
        float corr1 = __expf(m1 - mn1);
        m0 = mn0; m1 = mn1;

        float rs0 = 0.f, rs1 = 0.f;
        #pragma unroll
        for (int a = 0; a < 8; a++) {
            s[a][0] = __expf(s[a][0] - mn0);
            s[a][1] = __expf(s[a][1] - mn0);
            s[a][2] = __expf(s[a][2] - mn1);
            s[a][3] = __expf(s[a][3] - mn1);
            rs0 += s[a][0] + s[a][1];
            rs1 += s[a][2] + s[a][3];
        }
        #pragma unroll
        for (int off = 1; off <= 2; off <<= 1) {
            rs0 += __shfl_xor_sync(0xffffffffu, rs0, off);
            rs1 += __shfl_xor_sync(0xffffffffu, rs1, off);
        }
        l0 = l0 * corr0 + rs0;
        l1 = l1 * corr1 + rs1;
        #pragma unroll
        for (int n = 0; n < 5; n++) {
            o[n][0] *= corr0; o[n][1] *= corr0;
            o[n][2] *= corr1; o[n][3] *= corr1;
        }

        // ---- store P into warp-private band ----
        int pr0 = (w * 16 + g) * PS_STRIDE;
        int pr1 = pr0 + 8 * PS_STRIDE;
        #pragma unroll
        for (int a = 0; a < 8; a++) {
            __half2 h01 = __floats2half2_rn(s[a][0], s[a][1]);
            __half2 h23 = __floats2half2_rn(s[a][2], s[a][3]);
            Ps[pr0 + a * 4 + t] = *(uint32_t*)&h01;
            Ps[pr1 + a * 4 + t] = *(uint32_t*)&h23;
        }
        __syncwarp();

        // ---- O += P @ V (B-frags via ldmatrix.trans) ----
        #pragma unroll
        for (int ks = 0; ks < 4; ks++) {
            uint32_t pa0 = Ps[pr0 + ks * 8 + t];
            uint32_t pa1 = Ps[pr1 + ks * 8 + t];
            uint32_t pa2 = Ps[pr0 + ks * 8 + t + 4];
            uint32_t pa3 = Ps[pr1 + ks * 8 + t + 4];
            uint32_t vk = vrow + ks * (16 * VS_STRIDE * 4);
            #pragma unroll
            for (int n = 0; n < 5; n++) {
                uint32_t b0, b1;
                ldmatrix_x2_trans(b0, b1, vk + n * 16);
                mma_f16(o[n], pa0, pa1, pa2, pa3, b0, b1);
            }
        }
        __syncwarp();
    }

    // ---- epilogue: O/l -> (hi,lo) fp16 ctx split ----
    float inv0 = 1.f / l0;
    float inv1 = 1.f / l1;
    int r0 = q0 + w * 16 + g;
    uint32_t* ch32 = (uint32_t*)g_ch;
    uint32_t* cl32 = (uint32_t*)g_cl;
    #pragma unroll
    for (int n = 0; n < 5; n++) {
        int colu = hoff + 4 * n + t;
        float v00 = o[n][0] * inv0, v01 = o[n][1] * inv0;
        float v10 = o[n][2] * inv1, v11 = o[n][3] * inv1;
        __half2 h0 = __floats2half2_rn(v00, v01);
        __half2 h1 = __floats2half2_rn(v10, v11);
        __half2 e0 = __floats2half2_rn(v00 - __half2float(__low2half(h0)),
                                       v01 - __half2float(__high2half(h0)));
        __half2 e1 = __floats2half2_rn(v10 - __half2float(__low2half(h1)),
                                       v11 - __half2float(__high2half(h1)));
        ch32[r0 * DU32 + colu] = *(uint32_t*)&h0;
        cl32[r0 * DU32 + colu] = *(uint32_t*)&e0;
        ch32[(r0 + 8) * DU32 + colu] = *(uint32_t*)&h1;
        cl32[(r0 + 8) * DU32 + colu] = *(uint32_t*)&e1;
    }
}

// ============================================================
extern "C" void kernel_launch(void* const* d_in, const int* in_sizes, int n_in,
                              void* d_out, int out_size)
{
    const float* x  = (const float*)d_in[0];
    const float* Wq = (const float*)d_in[1];
    const float* Wk = (const float*)d_in[2];
    const float* Wv = (const float*)d_in[3];
    const float* Wo = (const float*)d_in[4];
    const float* bo = (const float*)d_in[5];
    float* out = (float*)d_out;

    convert_x_kernel<<<(S_LEN * D_MODEL + 255) / 256, 256>>>(x);
    convert_w_kernel<<<dim3((D_MODEL * D_MODEL + 255) / 256, 1, 4), 256>>>(Wq, Wk, Wv, Wo);

    gemm_qkv_h<<<dim3(S_LEN / 128, D_MODEL / 64, 3), 256>>>();
    attn_kernel<<<dim3(S_LEN / BR, NH), 256>>>();
    gemm_out_h<<<dim3(S_LEN / 128, D_MODEL / 64), 256>>>(bo, out);
}

// round 5
// speedup vs baseline: 4.8996x; 1.6993x over previous
#include <cuda_runtime.h>
#include <cuda_fp16.h>
#include <stdint.h>
#include <math.h>

#define S_LEN 4096
#define D_MODEL 320
#define DU32 160          // D_MODEL halves as u32
#define NH 8
#define DH 40
#define BR 64
#define BC 64

// -------- scratch (device globals: allocation-free) --------
__device__ __half g_xh[S_LEN * D_MODEL];
__device__ __half g_xl[S_LEN * D_MODEL];
__device__ __half g_wh[4 * D_MODEL * D_MODEL];
__device__ __half g_wl[4 * D_MODEL * D_MODEL];
__device__ __half g_qh[S_LEN * D_MODEL];
__device__ __half g_kh[S_LEN * D_MODEL];
__device__ __half g_vh[S_LEN * D_MODEL];
__device__ __half g_ch[S_LEN * D_MODEL];
__device__ __half g_cl[S_LEN * D_MODEL];

// ============================================================
// conversion kernels: fp32 -> (hi, lo) fp16 split
// ============================================================
__global__ void __launch_bounds__(256) convert_x_kernel(const float* __restrict__ x)
{
    int i = blockIdx.x * 256 + threadIdx.x;
    if (i < S_LEN * D_MODEL) {
        float v = x[i];
        __half h = __float2half_rn(v);
        g_xh[i] = h;
        g_xl[i] = __float2half_rn(v - __half2float(h));
    }
}

__global__ void __launch_bounds__(256) convert_w_kernel(
    const float* __restrict__ Wq, const float* __restrict__ Wk,
    const float* __restrict__ Wv, const float* __restrict__ Wo)
{
    int z = blockIdx.z;
    const float* W = (z == 0) ? Wq : (z == 1) ? Wk : (z == 2) ? Wv : Wo;
    float scale = (z == 0) ? rsqrtf((float)DH) : 1.0f;
    int i = blockIdx.x * 256 + threadIdx.x;
    if (i < D_MODEL * D_MODEL) {
        float v = W[i] * scale;
        __half h = __float2half_rn(v);
        g_wh[z * D_MODEL * D_MODEL + i] = h;
        g_wl[z * D_MODEL * D_MODEL + i] = __float2half_rn(v - __half2float(h));
    }
}

// ============================================================
// HMMA / async helpers
// ============================================================
__device__ __forceinline__ void mma_f16(float c[4], uint32_t a0, uint32_t a1,
                                        uint32_t a2, uint32_t a3,
                                        uint32_t b0, uint32_t b1)
{
    asm volatile(
        "mma.sync.aligned.m16n8k16.row.col.f32.f16.f16.f32 "
        "{%0,%1,%2,%3}, {%4,%5,%6,%7}, {%8,%9}, {%0,%1,%2,%3};\n"
        : "+f"(c[0]), "+f"(c[1]), "+f"(c[2]), "+f"(c[3])
        : "r"(a0), "r"(a1), "r"(a2), "r"(a3), "r"(b0), "r"(b1));
}

__device__ __forceinline__ void ldmatrix_x2_trans(uint32_t& r0, uint32_t& r1, uint32_t addr)
{
    asm volatile("ldmatrix.sync.aligned.m8n8.x2.trans.shared.b16 {%0,%1}, [%2];"
                 : "=r"(r0), "=r"(r1) : "r"(addr));
}

#define CP_ASYNC16(dst, src) \
    asm volatile("cp.async.cg.shared.global [%0], [%1], 16;\n" :: "r"(dst), "l"(src))
#define CP_COMMIT() asm volatile("cp.async.commit_group;\n" ::: "memory")
#define CP_WAIT1() asm volatile("cp.async.wait_group 1;\n" ::: "memory")
#define CP_WAIT0() asm volatile("cp.async.wait_group 0;\n" ::: "memory")

// ============================================================
// Split-fp16 HMMA GEMM: C = A @ W^T, 3-term compensated.
// ============================================================
#define PA_STR 12

__global__ void __launch_bounds__(256) gemm_qkv_h()
{
    __shared__ __align__(16) uint32_t Ah[128 * PA_STR];
    __shared__ __align__(16) uint32_t Al[128 * PA_STR];
    __shared__ __align__(16) uint32_t Wh[64 * PA_STR];
    __shared__ __align__(16) uint32_t Wl[64 * PA_STR];

    const int z = blockIdx.z;
    const uint32_t* __restrict__ xh32 = (const uint32_t*)g_xh;
    const uint32_t* __restrict__ xl32 = (const uint32_t*)g_xl;
    const uint32_t* __restrict__ wh32 = (const uint32_t*)(g_wh + z * D_MODEL * D_MODEL);
    const uint32_t* __restrict__ wl32 = (const uint32_t*)(g_wl + z * D_MODEL * D_MODEL);
    uint32_t* __restrict__ out32 =
        (uint32_t*)((z == 0) ? g_qh : (z == 1) ? g_kh : g_vh);

    const int tid = threadIdx.x;
    const int w = tid >> 5;
    const int lane = tid & 31;
    const int g = lane >> 2;
    const int t = lane & 3;
    const int m0 = blockIdx.x * 128;
    const int n0 = blockIdx.y * 64;

    float acc[8][4] = {};

    for (int kb = 0; kb < 20; kb++) {
        __syncthreads();
        #pragma unroll
        for (int it = 0; it < 4; it++) {
            int idx = tid + it * 256;
            int r = idx >> 3, c = idx & 7;
            Ah[r * PA_STR + c] = xh32[(m0 + r) * DU32 + kb * 8 + c];
            Al[r * PA_STR + c] = xl32[(m0 + r) * DU32 + kb * 8 + c];
        }
        #pragma unroll
        for (int it = 0; it < 2; it++) {
            int idx = tid + it * 256;
            int r = idx >> 3, c = idx & 7;
            Wh[r * PA_STR + c] = wh32[(n0 + r) * DU32 + kb * 8 + c];
            Wl[r * PA_STR + c] = wl32[(n0 + r) * DU32 + kb * 8 + c];
        }
        __syncthreads();

        int r0 = (w * 16 + g) * PA_STR;
        int r1 = r0 + 8 * PA_STR;
        uint32_t ah0 = Ah[r0 + t], ah1 = Ah[r1 + t], ah2 = Ah[r0 + t + 4], ah3 = Ah[r1 + t + 4];
        uint32_t al0 = Al[r0 + t], al1 = Al[r1 + t], al2 = Al[r0 + t + 4], al3 = Al[r1 + t + 4];

        #pragma unroll
        for (int a = 0; a < 8; a++) {
            int br = (a * 8 + g) * PA_STR;
            uint32_t bh0 = Wh[br + t], bh1 = Wh[br + t + 4];
            uint32_t bl0 = Wl[br + t], bl1 = Wl[br + t + 4];
            mma_f16(acc[a], ah0, ah1, ah2, ah3, bh0, bh1);
            mma_f16(acc[a], al0, al1, al2, al3, bh0, bh1);
            mma_f16(acc[a], ah0, ah1, ah2, ah3, bl0, bl1);
        }
    }

    int row = m0 + w * 16 + g;
    #pragma unroll
    for (int a = 0; a < 8; a++) {
        int colu = (n0 >> 1) + 4 * a + t;
        __half2 v0 = __floats2half2_rn(acc[a][0], acc[a][1]);
        __half2 v1 = __floats2half2_rn(acc[a][2], acc[a][3]);
        out32[row * DU32 + colu] = *(uint32_t*)&v0;
        out32[(row + 8) * DU32 + colu] = *(uint32_t*)&v1;
    }
}

__global__ void __launch_bounds__(256) gemm_out_h(
    const float* __restrict__ bo, float* __restrict__ out)
{
    __shared__ __align__(16) uint32_t Ah[128 * PA_STR];
    __shared__ __align__(16) uint32_t Al[128 * PA_STR];
    __shared__ __align__(16) uint32_t Wh[64 * PA_STR];
    __shared__ __align__(16) uint32_t Wl[64 * PA_STR];

    const uint32_t* __restrict__ xh32 = (const uint32_t*)g_ch;
    const uint32_t* __restrict__ xl32 = (const uint32_t*)g_cl;
    const uint32_t* __restrict__ wh32 = (const uint32_t*)(g_wh + 3 * D_MODEL * D_MODEL);
    const uint32_t* __restrict__ wl32 = (const uint32_t*)(g_wl + 3 * D_MODEL * D_MODEL);

    const int tid = threadIdx.x;
    const int w = tid >> 5;
    const int lane = tid & 31;
    const int g = lane >> 2;
    const int t = lane & 3;
    const int m0 = blockIdx.x * 128;
    const int n0 = blockIdx.y * 64;

    float acc[8][4] = {};

    for (int kb = 0; kb < 20; kb++) {
        __syncthreads();
        #pragma unroll
        for (int it = 0; it < 4; it++) {
            int idx = tid + it * 256;
            int r = idx >> 3, c = idx & 7;
            Ah[r * PA_STR + c] = xh32[(m0 + r) * DU32 + kb * 8 + c];
            Al[r * PA_STR + c] = xl32[(m0 + r) * DU32 + kb * 8 + c];
        }
        #pragma unroll
        for (int it = 0; it < 2; it++) {
            int idx = tid + it * 256;
            int r = idx >> 3, c = idx & 7;
            Wh[r * PA_STR + c] = wh32[(n0 + r) * DU32 + kb * 8 + c];
            Wl[r * PA_STR + c] = wl32[(n0 + r) * DU32 + kb * 8 + c];
        }
        __syncthreads();

        int r0 = (w * 16 + g) * PA_STR;
        int r1 = r0 + 8 * PA_STR;
        uint32_t ah0 = Ah[r0 + t], ah1 = Ah[r1 + t], ah2 = Ah[r0 + t + 4], ah3 = Ah[r1 + t + 4];
        uint32_t al0 = Al[r0 + t], al1 = Al[r1 + t], al2 = Al[r0 + t + 4], al3 = Al[r1 + t + 4];

        #pragma unroll
        for (int a = 0; a < 8; a++) {
            int br = (a * 8 + g) * PA_STR;
            uint32_t bh0 = Wh[br + t], bh1 = Wh[br + t + 4];
            uint32_t bl0 = Wl[br + t], bl1 = Wl[br + t + 4];
            mma_f16(acc[a], ah0, ah1, ah2, ah3, bh0, bh1);
            mma_f16(acc[a], al0, al1, al2, al3, bh0, bh1);
            mma_f16(acc[a], ah0, ah1, ah2, ah3, bl0, bl1);
        }
    }

    int row = m0 + w * 16 + g;
    #pragma unroll
    for (int a = 0; a < 8; a++) {
        int col = n0 + 8 * a + 2 * t;
        float b0v = bo[col], b1v = bo[col + 1];
        float2 v0 = make_float2(acc[a][0] + b0v, acc[a][1] + b1v);
        float2 v1 = make_float2(acc[a][2] + b0v, acc[a][3] + b1v);
        *(float2*)&out[row * D_MODEL + col] = v0;
        *(float2*)&out[(row + 8) * D_MODEL + col] = v1;
    }
}

// ============================================================
// Flash attention, double-buffered cp.async pipeline.
// CTA = 64 queries x 1 head, 4 warps (each m16 x n64 tile).
// ============================================================
#define QS_STRIDE 28
#define KS_STRIDE 28
#define VS_STRIDE 28
#define PS_STRIDE 36
#define KV_TILE (64 * 28)          // u32 per stage
#define KV_TILE_B (KV_TILE * 4)    // bytes per stage

__global__ void __launch_bounds__(128) attn_kernel()
{
    __shared__ __align__(16) uint32_t Qs[64 * QS_STRIDE];
    __shared__ __align__(16) uint32_t Ks[2 * KV_TILE];
    __shared__ __align__(16) uint32_t Vs[2 * KV_TILE];
    __shared__ __align__(16) uint32_t Ps[64 * PS_STRIDE];

    const uint32_t* __restrict__ q32 = (const uint32_t*)g_qh;
    const uint32_t* __restrict__ k32 = (const uint32_t*)g_kh;
    const uint32_t* __restrict__ v32 = (const uint32_t*)g_vh;

    const int tid = threadIdx.x;
    const int w = tid >> 5;
    const int lane = tid & 31;
    const int g = lane >> 2;
    const int t = lane & 3;
    const int head = blockIdx.y;
    const int q0 = blockIdx.x * BR;
    const int hoff = head * (DH / 2);   // u32 col offset

    const uint32_t ks_sh = (uint32_t)__cvta_generic_to_shared(&Ks[0]);
    const uint32_t vs_sh = (uint32_t)__cvta_generic_to_shared(&Vs[0]);

    // ---- zero K pad columns (cols 20..23, both stages, once) ----
    for (int idx = tid; idx < 2 * 64 * 4; idx += 128) {
        int st = idx >> 8;
        int rem = idx & 255;
        int r = rem >> 2, c = 20 + (rem & 3);
        Ks[st * KV_TILE + r * KS_STRIDE + c] = 0u;
    }

    // ---- load Q tile: 64 x 24 u32 (20 data + 4 zero) ----
    for (int idx = tid; idx < 64 * 24; idx += 128) {
        int r = idx / 24, c = idx % 24;
        Qs[r * QS_STRIDE + c] = (c < 20) ? q32[(q0 + r) * DU32 + hoff + c] : 0u;
    }

    // ---- issue stage 0 K/V loads ----
    {
        const int kb = 0, st = 0;
        for (int idx = tid; idx < 640; idx += 128) {
            int i2 = idx;
            bool isV = i2 >= 320;
            if (isV) i2 -= 320;
            int r = i2 / 5, c = i2 % 5;
            const uint32_t* src = (isV ? v32 : k32) + (kb + r) * DU32 + hoff + c * 4;
            uint32_t dst = (isV ? vs_sh : ks_sh) + st * KV_TILE_B + (r * KS_STRIDE + c * 4) * 4;
            CP_ASYNC16(dst, src);
        }
        CP_COMMIT();
    }
    __syncthreads();

    // ---- Q A-fragments register-resident ----
    uint32_t qa[3][4];
    {
        int r0 = (w * 16 + g) * QS_STRIDE;
        int r1 = r0 + 8 * QS_STRIDE;
        #pragma unroll
        for (int ks = 0; ks < 3; ks++) {
            qa[ks][0] = Qs[r0 + ks * 8 + t];
            qa[ks][1] = Qs[r1 + ks * 8 + t];
            qa[ks][2] = Qs[r0 + ks * 8 + t + 4];
            qa[ks][3] = Qs[r1 + ks * 8 + t + 4];
        }
    }

    float m0 = -1e30f, m1 = -1e30f;
    float l0 = 0.f, l1 = 0.f;
    float o[5][4] = {};

    const int NIT = S_LEN / BC;
    for (int iter = 0; iter < NIT; iter++) {
        const int st = iter & 1;

        // ---- prefetch next stage ----
        if (iter + 1 < NIT) {
            const int kb = (iter + 1) * BC;
            const int stn = (iter + 1) & 1;
            for (int idx = tid; idx < 640; idx += 128) {
                int i2 = idx;
                bool isV = i2 >= 320;
                if (isV) i2 -= 320;
                int r = i2 / 5, c = i2 % 5;
                const uint32_t* src = (isV ? v32 : k32) + (kb + r) * DU32 + hoff + c * 4;
                uint32_t dst = (isV ? vs_sh : ks_sh) + stn * KV_TILE_B + (r * KS_STRIDE + c * 4) * 4;
                CP_ASYNC16(dst, src);
            }
            CP_COMMIT();
            CP_WAIT1();
        } else {
            CP_WAIT0();
        }
        __syncthreads();

        const uint32_t* Kst = &Ks[st * KV_TILE];
        const uint32_t vrow = vs_sh + st * KV_TILE_B + (lane & 15) * (VS_STRIDE * 4);

        // ---- S = Q K^T ----
        float s[8][4];
        #pragma unroll
        for (int a = 0; a < 8; a++)
            #pragma unroll
            for (int j = 0; j < 4; j++) s[a][j] = 0.f;

        #pragma unroll
        for (int ks = 0; ks < 3; ks++) {
            #pragma unroll
            for (int a = 0; a < 8; a++) {
                int kr = (a * 8 + g) * KS_STRIDE + ks * 8 + t;
                mma_f16(s[a], qa[ks][0], qa[ks][1], qa[ks][2], qa[ks][3],
                        Kst[kr], Kst[kr + 4]);
            }
        }

        // ---- online softmax ----
        float rm0 = -1e30f, rm1 = -1e30f;
        #pragma unroll
        for (int a = 0; a < 8; a++) {
            rm0 = fmaxf(rm0, fmaxf(s[a][0], s[a][1]));
            rm1 = fmaxf(rm1, fmaxf(s[a][2], s[a][3]));
        }
        #pragma unroll
        for (int off = 1; off <= 2; off <<= 1) {
            rm0 = fmaxf(rm0, __shfl_xor_sync(0xffffffffu, rm0, off));
            rm1 = fmaxf(rm1, __shfl_xor_sync(0xffffffffu, rm1, off));
        }
        float mn0 = fmaxf(m0, rm0);
        float mn1 = fmaxf(m1, rm1);
        float corr0 = __expf(m0 - mn0);
        float corr1 = __expf(m1 - mn1);
        m0 = mn0; m1 = mn1;

        float rs0 = 0.f, rs1 = 0.f;
        #pragma unroll
        for (int a = 0; a < 8; a++) {
            s[a][0] = __expf(s[a][0] - mn0);
            s[a][1] = __expf(s[a][1] - mn0);
            s[a][2] = __expf(s[a][2] - mn1);
            s[a][3] = __expf(s[a][3] - mn1);
            rs0 += s[a][0] + s[a][1];
            rs1 += s[a][2] + s[a][3];
        }
        #pragma unroll
        for (int off = 1; off <= 2; off <<= 1) {
            rs0 += __shfl_xor_sync(0xffffffffu, rs0, off);
            rs1 += __shfl_xor_sync(0xffffffffu, rs1, off);
        }
        l0 = l0 * corr0 + rs0;
        l1 = l1 * corr1 + rs1;
        #pragma unroll
        for (int n = 0; n < 5; n++) {
            o[n][0] *= corr0; o[n][1] *= corr0;
            o[n][2] *= corr1; o[n][3] *= corr1;
        }

        // ---- store P into warp-private band ----
        int pr0 = (w * 16 + g) * PS_STRIDE;
        int pr1 = pr0 + 8 * PS_STRIDE;
        #pragma unroll
        for (int a = 0; a < 8; a++) {
            __half2 h01 = __floats2half2_rn(s[a][0], s[a][1]);
            __half2 h23 = __floats2half2_rn(s[a][2], s[a][3]);
            Ps[pr0 + a * 4 + t] = *(uint32_t*)&h01;
            Ps[pr1 + a * 4 + t] = *(uint32_t*)&h23;
        }
        __syncwarp();

        // ---- O += P @ V ----
        #pragma unroll
        for (int ks = 0; ks < 4; ks++) {
            uint32_t pa0 = Ps[pr0 + ks * 8 + t];
            uint32_t pa1 = Ps[pr1 + ks * 8 + t];
            uint32_t pa2 = Ps[pr0 + ks * 8 + t + 4];
            uint32_t pa3 = Ps[pr1 + ks * 8 + t + 4];
            uint32_t vk = vrow + ks * (16 * VS_STRIDE * 4);
            #pragma unroll
            for (int n = 0; n < 5; n++) {
                uint32_t b0, b1;
                ldmatrix_x2_trans(b0, b1, vk + n * 16);
                mma_f16(o[n], pa0, pa1, pa2, pa3, b0, b1);
            }
        }
        __syncthreads();  // all reads of stage st done before overwrite
    }

    // ---- epilogue: O/l -> (hi,lo) fp16 ctx split ----
    float inv0 = 1.f / l0;
    float inv1 = 1.f / l1;
    int r0 = q0 + w * 16 + g;
    uint32_t* ch32 = (uint32_t*)g_ch;
    uint32_t* cl32 = (uint32_t*)g_cl;
    #pragma unroll
    for (int n = 0; n < 5; n++) {
        int colu = hoff + 4 * n + t;
        float v00 = o[n][0] * inv0, v01 = o[n][1] * inv0;
        float v10 = o[n][2] * inv1, v11 = o[n][3] * inv1;
        __half2 h0 = __floats2half2_rn(v00, v01);
        __half2 h1 = __floats2half2_rn(v10, v11);
        __half2 e0 = __floats2half2_rn(v00 - __half2float(__low2half(h0)),
                                       v01 - __half2float(__high2half(h0)));
        __half2 e1 = __floats2half2_rn(v10 - __half2float(__low2half(h1)),
                                       v11 - __half2float(__high2half(h1)));
        ch32[r0 * DU32 + colu] = *(uint32_t*)&h0;
        cl32[r0 * DU32 + colu] = *(uint32_t*)&e0;
        ch32[(r0 + 8) * DU32 + colu] = *(uint32_t*)&h1;
        cl32[(r0 + 8) * DU32 + colu] = *(uint32_t*)&e1;
    }
}

// ============================================================
extern "C" void kernel_launch(void* const* d_in, const int* in_sizes, int n_in,
                              void* d_out, int out_size)
{
    const float* x  = (const float*)d_in[0];
    const float* Wq = (const float*)d_in[1];
    const float* Wk = (const float*)d_in[2];
    const float* Wv = (const float*)d_in[3];
    const float* Wo = (const float*)d_in[4];
    const float* bo = (const float*)d_in[5];
    float* out = (float*)d_out;

    convert_x_kernel<<<(S_LEN * D_MODEL + 255) / 256, 256>>>(x);
    convert_w_kernel<<<dim3((D_MODEL * D_MODEL + 255) / 256, 1, 4), 256>>>(Wq, Wk, Wv, Wo);

    gemm_qkv_h<<<dim3(S_LEN / 128, D_MODEL / 64, 3), 256>>>();
    attn_kernel<<<dim3(S_LEN / BR, NH), 128>>>();
    gemm_out_h<<<dim3(S_LEN / 128, D_MODEL / 64), 256>>>(bo, out);
}

// round 6
// speedup vs baseline: 5.8770x; 1.1995x over previous
#include <cuda_runtime.h>
#include <cuda_fp16.h>
#include <stdint.h>
#include <math.h>

#define S_LEN 4096
#define D_MODEL 320
#define DU32 160          // D_MODEL halves as u32
#define NH 8
#define DH 40
#define BR 64
#define BC 64
#define LOG2E 1.4426950408889634f

// -------- scratch (device globals: allocation-free) --------
__device__ __half g_xh[S_LEN * D_MODEL];
__device__ __half g_xl[S_LEN * D_MODEL];
__device__ __half g_wh[4 * D_MODEL * D_MODEL];
__device__ __half g_wl[4 * D_MODEL * D_MODEL];
__device__ __half g_qh[S_LEN * D_MODEL];
__device__ __half g_kh[S_LEN * D_MODEL];
__device__ __half g_vh[S_LEN * D_MODEL];
__device__ __half g_ch[S_LEN * D_MODEL];
__device__ __half g_cl[S_LEN * D_MODEL];

// ============================================================
// conversion kernels: fp32 -> (hi, lo) fp16 split
// ============================================================
__global__ void __launch_bounds__(256) convert_x_kernel(const float* __restrict__ x)
{
    int i = blockIdx.x * 256 + threadIdx.x;
    if (i < S_LEN * D_MODEL) {
        float v = x[i];
        __half h = __float2half_rn(v);
        g_xh[i] = h;
        g_xl[i] = __float2half_rn(v - __half2float(h));
    }
}

__global__ void __launch_bounds__(256) convert_w_kernel(
    const float* __restrict__ Wq, const float* __restrict__ Wk,
    const float* __restrict__ Wv, const float* __restrict__ Wo)
{
    int z = blockIdx.z;
    const float* W = (z == 0) ? Wq : (z == 1) ? Wk : (z == 2) ? Wv : Wo;
    // fold softmax scale AND log2(e) into Wq: S comes out in log2 domain
    float scale = (z == 0) ? rsqrtf((float)DH) * LOG2E : 1.0f;
    int i = blockIdx.x * 256 + threadIdx.x;
    if (i < D_MODEL * D_MODEL) {
        float v = W[i] * scale;
        __half h = __float2half_rn(v);
        g_wh[z * D_MODEL * D_MODEL + i] = h;
        g_wl[z * D_MODEL * D_MODEL + i] = __float2half_rn(v - __half2float(h));
    }
}

// ============================================================
// HMMA / async helpers
// ============================================================
__device__ __forceinline__ void mma_f16(float c[4], uint32_t a0, uint32_t a1,
                                        uint32_t a2, uint32_t a3,
                                        uint32_t b0, uint32_t b1)
{
    asm volatile(
        "mma.sync.aligned.m16n8k16.row.col.f32.f16.f16.f32 "
        "{%0,%1,%2,%3}, {%4,%5,%6,%7}, {%8,%9}, {%0,%1,%2,%3};\n"
        : "+f"(c[0]), "+f"(c[1]), "+f"(c[2]), "+f"(c[3])
        : "r"(a0), "r"(a1), "r"(a2), "r"(a3), "r"(b0), "r"(b1));
}

__device__ __forceinline__ void ldmatrix_x2_trans(uint32_t& r0, uint32_t& r1, uint32_t addr)
{
    asm volatile("ldmatrix.sync.aligned.m8n8.x2.trans.shared.b16 {%0,%1}, [%2];"
                 : "=r"(r0), "=r"(r1) : "r"(addr));
}

__device__ __forceinline__ uint32_t exp2_f16x2(float s0, float s1)
{
    __half2 h = __floats2half2_rn(s0, s1);
    uint32_t r;
    asm volatile("ex2.approx.f16x2 %0, %1;" : "=r"(r) : "r"(*(uint32_t*)&h));
    return r;
}

#define CP_ASYNC16(dst, src) \
    asm volatile("cp.async.cg.shared.global [%0], [%1], 16;\n" :: "r"(dst), "l"(src))
#define CP_COMMIT() asm volatile("cp.async.commit_group;\n" ::: "memory")
#define CP_WAIT1() asm volatile("cp.async.wait_group 1;\n" ::: "memory")
#define CP_WAIT0() asm volatile("cp.async.wait_group 0;\n" ::: "memory")

// ============================================================
// Split-fp16 HMMA GEMM: C = A @ W^T, 3-term compensated.
// ============================================================
#define PA_STR 12

__global__ void __launch_bounds__(256) gemm_qkv_h()
{
    __shared__ __align__(16) uint32_t Ah[128 * PA_STR];
    __shared__ __align__(16) uint32_t Al[128 * PA_STR];
    __shared__ __align__(16) uint32_t Wh[64 * PA_STR];
    __shared__ __align__(16) uint32_t Wl[64 * PA_STR];

    const int z = blockIdx.z;
    const uint32_t* __restrict__ xh32 = (const uint32_t*)g_xh;
    const uint32_t* __restrict__ xl32 = (const uint32_t*)g_xl;
    const uint32_t* __restrict__ wh32 = (const uint32_t*)(g_wh + z * D_MODEL * D_MODEL);
    const uint32_t* __restrict__ wl32 = (const uint32_t*)(g_wl + z * D_MODEL * D_MODEL);
    uint32_t* __restrict__ out32 =
        (uint32_t*)((z == 0) ? g_qh : (z == 1) ? g_kh : g_vh);

    const int tid = threadIdx.x;
    const int w = tid >> 5;
    const int lane = tid & 31;
    const int g = lane >> 2;
    const int t = lane & 3;
    const int m0 = blockIdx.x * 128;
    const int n0 = blockIdx.y * 64;

    float acc[8][4] = {};

    for (int kb = 0; kb < 20; kb++) {
        __syncthreads();
        #pragma unroll
        for (int it = 0; it < 4; it++) {
            int idx = tid + it * 256;
            int r = idx >> 3, c = idx & 7;
            Ah[r * PA_STR + c] = xh32[(m0 + r) * DU32 + kb * 8 + c];
            Al[r * PA_STR + c] = xl32[(m0 + r) * DU32 + kb * 8 + c];
        }
        #pragma unroll
        for (int it = 0; it < 2; it++) {
            int idx = tid + it * 256;
            int r = idx >> 3, c = idx & 7;
            Wh[r * PA_STR + c] = wh32[(n0 + r) * DU32 + kb * 8 + c];
            Wl[r * PA_STR + c] = wl32[(n0 + r) * DU32 + kb * 8 + c];
        }
        __syncthreads();

        int r0 = (w * 16 + g) * PA_STR;
        int r1 = r0 + 8 * PA_STR;
        uint32_t ah0 = Ah[r0 + t], ah1 = Ah[r1 + t], ah2 = Ah[r0 + t + 4], ah3 = Ah[r1 + t + 4];
        uint32_t al0 = Al[r0 + t], al1 = Al[r1 + t], al2 = Al[r0 + t + 4], al3 = Al[r1 + t + 4];

        #pragma unroll
        for (int a = 0; a < 8; a++) {
            int br = (a * 8 + g) * PA_STR;
            uint32_t bh0 = Wh[br + t], bh1 = Wh[br + t + 4];
            uint32_t bl0 = Wl[br + t], bl1 = Wl[br + t + 4];
            mma_f16(acc[a], ah0, ah1, ah2, ah3, bh0, bh1);
            mma_f16(acc[a], al0, al1, al2, al3, bh0, bh1);
            mma_f16(acc[a], ah0, ah1, ah2, ah3, bl0, bl1);
        }
    }

    int row = m0 + w * 16 + g;
    #pragma unroll
    for (int a = 0; a < 8; a++) {
        int colu = (n0 >> 1) + 4 * a + t;
        __half2 v0 = __floats2half2_rn(acc[a][0], acc[a][1]);
        __half2 v1 = __floats2half2_rn(acc[a][2], acc[a][3]);
        out32[row * DU32 + colu] = *(uint32_t*)&v0;
        out32[(row + 8) * DU32 + colu] = *(uint32_t*)&v1;
    }
}

__global__ void __launch_bounds__(256) gemm_out_h(
    const float* __restrict__ bo, float* __restrict__ out)
{
    __shared__ __align__(16) uint32_t Ah[128 * PA_STR];
    __shared__ __align__(16) uint32_t Al[128 * PA_STR];
    __shared__ __align__(16) uint32_t Wh[64 * PA_STR];
    __shared__ __align__(16) uint32_t Wl[64 * PA_STR];

    const uint32_t* __restrict__ xh32 = (const uint32_t*)g_ch;
    const uint32_t* __restrict__ xl32 = (const uint32_t*)g_cl;
    const uint32_t* __restrict__ wh32 = (const uint32_t*)(g_wh + 3 * D_MODEL * D_MODEL);
    const uint32_t* __restrict__ wl32 = (const uint32_t*)(g_wl + 3 * D_MODEL * D_MODEL);

    const int tid = threadIdx.x;
    const int w = tid >> 5;
    const int lane = tid & 31;
    const int g = lane >> 2;
    const int t = lane & 3;
    const int m0 = blockIdx.x * 128;
    const int n0 = blockIdx.y * 64;

    float acc[8][4] = {};

    for (int kb = 0; kb < 20; kb++) {
        __syncthreads();
        #pragma unroll
        for (int it = 0; it < 4; it++) {
            int idx = tid + it * 256;
            int r = idx >> 3, c = idx & 7;
            Ah[r * PA_STR + c] = xh32[(m0 + r) * DU32 + kb * 8 + c];
            Al[r * PA_STR + c] = xl32[(m0 + r) * DU32 + kb * 8 + c];
        }
        #pragma unroll
        for (int it = 0; it < 2; it++) {
            int idx = tid + it * 256;
            int r = idx >> 3, c = idx & 7;
            Wh[r * PA_STR + c] = wh32[(n0 + r) * DU32 + kb * 8 + c];
            Wl[r * PA_STR + c] = wl32[(n0 + r) * DU32 + kb * 8 + c];
        }
        __syncthreads();

        int r0 = (w * 16 + g) * PA_STR;
        int r1 = r0 + 8 * PA_STR;
        uint32_t ah0 = Ah[r0 + t], ah1 = Ah[r1 + t], ah2 = Ah[r0 + t + 4], ah3 = Ah[r1 + t + 4];
        uint32_t al0 = Al[r0 + t], al1 = Al[r1 + t], al2 = Al[r0 + t + 4], al3 = Al[r1 + t + 4];

        #pragma unroll
        for (int a = 0; a < 8; a++) {
            int br = (a * 8 + g) * PA_STR;
            uint32_t bh0 = Wh[br + t], bh1 = Wh[br + t + 4];
            uint32_t bl0 = Wl[br + t], bl1 = Wl[br + t + 4];
            mma_f16(acc[a], ah0, ah1, ah2, ah3, bh0, bh1);
            mma_f16(acc[a], al0, al1, al2, al3, bh0, bh1);
            mma_f16(acc[a], ah0, ah1, ah2, ah3, bl0, bl1);
        }
    }

    int row = m0 + w * 16 + g;
    #pragma unroll
    for (int a = 0; a < 8; a++) {
        int col = n0 + 8 * a + 2 * t;
        float b0v = bo[col], b1v = bo[col + 1];
        float2 v0 = make_float2(acc[a][0] + b0v, acc[a][1] + b1v);
        float2 v1 = make_float2(acc[a][2] + b0v, acc[a][3] + b1v);
        *(float2*)&out[row * D_MODEL + col] = v0;
        *(float2*)&out[(row + 8) * D_MODEL + col] = v1;
    }
}

// ============================================================
// Flash attention: fixed-base exp2 softmax, register-resident P,
// l via ones-column PV atom, double-buffered cp.async K/V.
// CTA = 64 queries x 1 head, 4 warps (each m16 x n64 tile).
// ============================================================
#define QS_STRIDE 28
#define KS_STRIDE 28
#define VS_STRIDE 28
#define KV_TILE (64 * 28)
#define KV_TILE_B (KV_TILE * 4)

__global__ void __launch_bounds__(128) attn_kernel()
{
    __shared__ __align__(16) uint32_t Qs[64 * QS_STRIDE];
    __shared__ __align__(16) uint32_t Ks[2 * KV_TILE];
    __shared__ __align__(16) uint32_t Vs[2 * KV_TILE];

    const uint32_t* __restrict__ q32 = (const uint32_t*)g_qh;
    const uint32_t* __restrict__ k32 = (const uint32_t*)g_kh;
    const uint32_t* __restrict__ v32 = (const uint32_t*)g_vh;

    const int tid = threadIdx.x;
    const int w = tid >> 5;
    const int lane = tid & 31;
    const int g = lane >> 2;
    const int t = lane & 3;
    const int head = blockIdx.y;
    const int q0 = blockIdx.x * BR;
    const int hoff = head * (DH / 2);

    const uint32_t ks_sh = (uint32_t)__cvta_generic_to_shared(&Ks[0]);
    const uint32_t vs_sh = (uint32_t)__cvta_generic_to_shared(&Vs[0]);

    // ---- prologue: K pad cols zero; V col 20 = (1,1) ones, 21..23 zero ----
    for (int idx = tid; idx < 2 * 64 * 4; idx += 128) {
        int st = idx >> 8;
        int rem = idx & 255;
        int r = rem >> 2, c = 20 + (rem & 3);
        Ks[st * KV_TILE + r * KS_STRIDE + c] = 0u;
        Vs[st * KV_TILE + r * VS_STRIDE + c] = (c == 20) ? 0x3C003C00u : 0u;
    }

    // ---- load Q tile: 64 x 24 u32 (20 data + 4 zero) ----
    for (int idx = tid; idx < 64 * 24; idx += 128) {
        int r = idx / 24, c = idx % 24;
        Qs[r * QS_STRIDE + c] = (c < 20) ? q32[(q0 + r) * DU32 + hoff + c] : 0u;
    }

    // ---- hoisted cp.async addressing (5 chunks per thread) ----
    const uint32_t* srcPtr[5];
    uint32_t dstOff[5];
    #pragma unroll
    for (int j = 0; j < 5; j++) {
        int idx = tid + j * 128;
        int i2 = idx;
        bool isV = i2 >= 320;
        if (isV) i2 -= 320;
        int r = i2 / 5, c = i2 % 5;
        srcPtr[j] = (isV ? v32 : k32) + r * DU32 + hoff + c * 4;
        dstOff[j] = (isV ? vs_sh : ks_sh) + (r * KS_STRIDE + c * 4) * 4;
    }

    // ---- issue stage 0 loads ----
    #pragma unroll
    for (int j = 0; j < 5; j++) {
        CP_ASYNC16(dstOff[j], srcPtr[j]);
        srcPtr[j] += BC * DU32;
    }
    CP_COMMIT();
    __syncthreads();

    // ---- Q A-fragments register-resident ----
    uint32_t qa[3][4];
    {
        int r0 = (w * 16 + g) * QS_STRIDE;
        int r1 = r0 + 8 * QS_STRIDE;
        #pragma unroll
        for (int ks = 0; ks < 3; ks++) {
            qa[ks][0] = Qs[r0 + ks * 8 + t];
            qa[ks][1] = Qs[r1 + ks * 8 + t];
            qa[ks][2] = Qs[r0 + ks * 8 + t + 4];
            qa[ks][3] = Qs[r1 + ks * 8 + t + 4];
        }
    }

    float o[6][4] = {};   // atoms 0..4 = output cols, atom 5 col 40 = l

    const int NIT = S_LEN / BC;
    for (int iter = 0; iter < NIT; iter++) {
        const int st = iter & 1;

        if (iter + 1 < NIT) {
            const uint32_t so = ((iter + 1) & 1) * KV_TILE_B;
            #pragma unroll
            for (int j = 0; j < 5; j++) {
                CP_ASYNC16(dstOff[j] + so, srcPtr[j]);
                srcPtr[j] += BC * DU32;
            }
            CP_COMMIT();
            CP_WAIT1();
        } else {
            CP_WAIT0();
        }
        __syncthreads();

        const uint32_t* Kst = &Ks[st * KV_TILE];
        const uint32_t vrow = vs_sh + st * KV_TILE_B + (lane & 15) * (VS_STRIDE * 4);

        // ---- S = Q K^T (log2-domain: scale*log2e folded into Wq) ----
        float s[8][4];
        #pragma unroll
        for (int a = 0; a < 8; a++)
            #pragma unroll
            for (int j = 0; j < 4; j++) s[a][j] = 0.f;

        #pragma unroll
        for (int ks = 0; ks < 3; ks++) {
            #pragma unroll
            for (int a = 0; a < 8; a++) {
                int kr = (a * 8 + g) * KS_STRIDE + ks * 8 + t;
                mma_f16(s[a], qa[ks][0], qa[ks][1], qa[ks][2], qa[ks][3],
                        Kst[kr], Kst[kr + 4]);
            }
        }

        // ---- P = 2^S directly into PV A-fragments (registers) ----
        uint32_t p01[8], p23[8];
        #pragma unroll
        for (int a = 0; a < 8; a++) {
            p01[a] = exp2_f16x2(s[a][0], s[a][1]);
            p23[a] = exp2_f16x2(s[a][2], s[a][3]);
        }

        // ---- O += P @ [V | 1] : 4 k-steps x 6 n-atoms ----
        #pragma unroll
        for (int ks = 0; ks < 4; ks++) {
            uint32_t vk = vrow + ks * (16 * VS_STRIDE * 4);
            #pragma unroll
            for (int n = 0; n < 6; n++) {
                uint32_t b0, b1;
                ldmatrix_x2_trans(b0, b1, vk + n * 16);
                mma_f16(o[n], p01[2 * ks], p23[2 * ks],
                        p01[2 * ks + 1], p23[2 * ks + 1], b0, b1);
            }
        }
        __syncthreads();  // stage st reads done before overwrite
    }

    // ---- epilogue: l = ones-column (col 40, held by t=0 lanes) ----
    float l0 = __shfl_sync(0xffffffffu, o[5][0], lane & 28);
    float l1 = __shfl_sync(0xffffffffu, o[5][2], lane & 28);
    float inv0 = 1.f / l0;
    float inv1 = 1.f / l1;
    int r0 = q0 + w * 16 + g;
    uint32_t* ch32 = (uint32_t*)g_ch;
    uint32_t* cl32 = (uint32_t*)g_cl;
    #pragma unroll
    for (int n = 0; n < 5; n++) {
        int colu = hoff + 4 * n + t;
        float v00 = o[n][0] * inv0, v01 = o[n][1] * inv0;
        float v10 = o[n][2] * inv1, v11 = o[n][3] * inv1;
        __half2 h0 = __floats2half2_rn(v00, v01);
        __half2 h1 = __floats2half2_rn(v10, v11);
        __half2 e0 = __floats2half2_rn(v00 - __half2float(__low2half(h0)),
                                       v01 - __half2float(__high2half(h0)));
        __half2 e1 = __floats2half2_rn(v10 - __half2float(__low2half(h1)),
                                       v11 - __half2float(__high2half(h1)));
        ch32[r0 * DU32 + colu] = *(uint32_t*)&h0;
        cl32[r0 * DU32 + colu] = *(uint32_t*)&e0;
        ch32[(r0 + 8) * DU32 + colu] = *(uint32_t*)&h1;
        cl32[(r0 + 8) * DU32 + colu] = *(uint32_t*)&e1;
    }
}

// ============================================================
extern "C" void kernel_launch(void* const* d_in, const int* in_sizes, int n_in,
                              void* d_out, int out_size)
{
    const float* x  = (const float*)d_in[0];
    const float* Wq = (const float*)d_in[1];
    const float* Wk = (const float*)d_in[2];
    const float* Wv = (const float*)d_in[3];
    const float* Wo = (const float*)d_in[4];
    const float* bo = (const float*)d_in[5];
    float* out = (float*)d_out;

    convert_x_kernel<<<(S_LEN * D_MODEL + 255) / 256, 256>>>(x);
    convert_w_kernel<<<dim3((D_MODEL * D_MODEL + 255) / 256, 1, 4), 256>>>(Wq, Wk, Wv, Wo);

    gemm_qkv_h<<<dim3(S_LEN / 128, D_MODEL / 64, 3), 256>>>();
    attn_kernel<<<dim3(S_LEN / BR, NH), 128>>>();
    gemm_out_h<<<dim3(S_LEN / 128, D_MODEL / 64), 256>>>(bo, out);
}

// round 7
// speedup vs baseline: 6.3634x; 1.0828x over previous
#include <cuda_runtime.h>
#include <cuda_fp16.h>
#include <stdint.h>
#include <math.h>

#define S_LEN 4096
#define D_MODEL 320
#define DU32 160          // D_MODEL halves as u32
#define NH 8
#define DH 40
#define BR 64
#define BC 64
#define NSPLIT 2
#define KRANGE (S_LEN / NSPLIT)
#define LOG2E 1.4426950408889634f

// -------- scratch (device globals: allocation-free) --------
__device__ __half g_xh[S_LEN * D_MODEL];
__device__ __half g_xl[S_LEN * D_MODEL];
__device__ __half g_wh[4 * D_MODEL * D_MODEL];
__device__ __half g_wl[4 * D_MODEL * D_MODEL];
__device__ __half g_qh[S_LEN * D_MODEL];
__device__ __half g_kh[S_LEN * D_MODEL];
__device__ __half g_vh[S_LEN * D_MODEL];
__device__ __half g_ch[S_LEN * D_MODEL];
__device__ __half g_cl[S_LEN * D_MODEL];
__device__ float  g_po[NSPLIT][S_LEN * D_MODEL];   // unnormalized O partials
__device__ float  g_pl[NSPLIT][NH * S_LEN];        // l partials

// ============================================================
// conversion kernels: fp32 -> (hi, lo) fp16 split
// ============================================================
__global__ void __launch_bounds__(256) convert_x_kernel(const float* __restrict__ x)
{
    int i = blockIdx.x * 256 + threadIdx.x;
    if (i < S_LEN * D_MODEL) {
        float v = x[i];
        __half h = __float2half_rn(v);
        g_xh[i] = h;
        g_xl[i] = __float2half_rn(v - __half2float(h));
    }
}

__global__ void __launch_bounds__(256) convert_w_kernel(
    const float* __restrict__ Wq, const float* __restrict__ Wk,
    const float* __restrict__ Wv, const float* __restrict__ Wo)
{
    int z = blockIdx.z;
    const float* W = (z == 0) ? Wq : (z == 1) ? Wk : (z == 2) ? Wv : Wo;
    float scale = (z == 0) ? rsqrtf((float)DH) * LOG2E : 1.0f;
    int i = blockIdx.x * 256 + threadIdx.x;
    if (i < D_MODEL * D_MODEL) {
        float v = W[i] * scale;
        __half h = __float2half_rn(v);
        g_wh[z * D_MODEL * D_MODEL + i] = h;
        g_wl[z * D_MODEL * D_MODEL + i] = __float2half_rn(v - __half2float(h));
    }
}

// ============================================================
// HMMA / async helpers
// ============================================================
__device__ __forceinline__ void mma_f16(float c[4], uint32_t a0, uint32_t a1,
                                        uint32_t a2, uint32_t a3,
                                        uint32_t b0, uint32_t b1)
{
    asm volatile(
        "mma.sync.aligned.m16n8k16.row.col.f32.f16.f16.f32 "
        "{%0,%1,%2,%3}, {%4,%5,%6,%7}, {%8,%9}, {%0,%1,%2,%3};\n"
        : "+f"(c[0]), "+f"(c[1]), "+f"(c[2]), "+f"(c[3])
        : "r"(a0), "r"(a1), "r"(a2), "r"(a3), "r"(b0), "r"(b1));
}

__device__ __forceinline__ void ldmatrix_x2_trans(uint32_t& r0, uint32_t& r1, uint32_t addr)
{
    asm volatile("ldmatrix.sync.aligned.m8n8.x2.trans.shared.b16 {%0,%1}, [%2];"
                 : "=r"(r0), "=r"(r1) : "r"(addr));
}

__device__ __forceinline__ uint32_t exp2_f16x2(float s0, float s1)
{
    __half2 h = __floats2half2_rn(s0, s1);
    uint32_t r;
    asm volatile("ex2.approx.f16x2 %0, %1;" : "=r"(r) : "r"(*(uint32_t*)&h));
    return r;
}

#define CP_ASYNC16(dst, src) \
    asm volatile("cp.async.cg.shared.global [%0], [%1], 16;\n" :: "r"(dst), "l"(src))
#define CP_COMMIT() asm volatile("cp.async.commit_group;\n" ::: "memory")
#define CP_WAIT1() asm volatile("cp.async.wait_group 1;\n" ::: "memory")
#define CP_WAIT0() asm volatile("cp.async.wait_group 0;\n" ::: "memory")

// ============================================================
// Split-fp16 HMMA GEMM: C = A @ W^T, 3-term compensated.
// qkv: BM=128 (8 warps), out: BM=64 (4 warps).
// ============================================================
#define PA_STR 12

__global__ void __launch_bounds__(256) gemm_qkv_h()
{
    __shared__ __align__(16) uint32_t Ah[128 * PA_STR];
    __shared__ __align__(16) uint32_t Al[128 * PA_STR];
    __shared__ __align__(16) uint32_t Wh[64 * PA_STR];
    __shared__ __align__(16) uint32_t Wl[64 * PA_STR];

    const int z = blockIdx.z;
    const uint32_t* __restrict__ xh32 = (const uint32_t*)g_xh;
    const uint32_t* __restrict__ xl32 = (const uint32_t*)g_xl;
    const uint32_t* __restrict__ wh32 = (const uint32_t*)(g_wh + z * D_MODEL * D_MODEL);
    const uint32_t* __restrict__ wl32 = (const uint32_t*)(g_wl + z * D_MODEL * D_MODEL);
    uint32_t* __restrict__ out32 =
        (uint32_t*)((z == 0) ? g_qh : (z == 1) ? g_kh : g_vh);

    const int tid = threadIdx.x;
    const int w = tid >> 5;
    const int lane = tid & 31;
    const int g = lane >> 2;
    const int t = lane & 3;
    const int m0 = blockIdx.x * 128;
    const int n0 = blockIdx.y * 64;

    float acc[8][4] = {};

    for (int kb = 0; kb < 20; kb++) {
        __syncthreads();
        #pragma unroll
        for (int it = 0; it < 4; it++) {
            int idx = tid + it * 256;
            int r = idx >> 3, c = idx & 7;
            Ah[r * PA_STR + c] = xh32[(m0 + r) * DU32 + kb * 8 + c];
            Al[r * PA_STR + c] = xl32[(m0 + r) * DU32 + kb * 8 + c];
        }
        #pragma unroll
        for (int it = 0; it < 2; it++) {
            int idx = tid + it * 256;
            int r = idx >> 3, c = idx & 7;
            Wh[r * PA_STR + c] = wh32[(n0 + r) * DU32 + kb * 8 + c];
            Wl[r * PA_STR + c] = wl32[(n0 + r) * DU32 + kb * 8 + c];
        }
        __syncthreads();

        int r0 = (w * 16 + g) * PA_STR;
        int r1 = r0 + 8 * PA_STR;
        uint32_t ah0 = Ah[r0 + t], ah1 = Ah[r1 + t], ah2 = Ah[r0 + t + 4], ah3 = Ah[r1 + t + 4];
        uint32_t al0 = Al[r0 + t], al1 = Al[r1 + t], al2 = Al[r0 + t + 4], al3 = Al[r1 + t + 4];

        #pragma unroll
        for (int a = 0; a < 8; a++) {
            int br = (a * 8 + g) * PA_STR;
            uint32_t bh0 = Wh[br + t], bh1 = Wh[br + t + 4];
            uint32_t bl0 = Wl[br + t], bl1 = Wl[br + t + 4];
            mma_f16(acc[a], ah0, ah1, ah2, ah3, bh0, bh1);
            mma_f16(acc[a], al0, al1, al2, al3, bh0, bh1);
            mma_f16(acc[a], ah0, ah1, ah2, ah3, bl0, bl1);
        }
    }

    int row = m0 + w * 16 + g;
    #pragma unroll
    for (int a = 0; a < 8; a++) {
        int colu = (n0 >> 1) + 4 * a + t;
        __half2 v0 = __floats2half2_rn(acc[a][0], acc[a][1]);
        __half2 v1 = __floats2half2_rn(acc[a][2], acc[a][3]);
        out32[row * DU32 + colu] = *(uint32_t*)&v0;
        out32[(row + 8) * DU32 + colu] = *(uint32_t*)&v1;
    }
}

__global__ void __launch_bounds__(128) gemm_out_h(
    const float* __restrict__ bo, float* __restrict__ out)
{
    __shared__ __align__(16) uint32_t Ah[64 * PA_STR];
    __shared__ __align__(16) uint32_t Al[64 * PA_STR];
    __shared__ __align__(16) uint32_t Wh[64 * PA_STR];
    __shared__ __align__(16) uint32_t Wl[64 * PA_STR];

    const uint32_t* __restrict__ xh32 = (const uint32_t*)g_ch;
    const uint32_t* __restrict__ xl32 = (const uint32_t*)g_cl;
    const uint32_t* __restrict__ wh32 = (const uint32_t*)(g_wh + 3 * D_MODEL * D_MODEL);
    const uint32_t* __restrict__ wl32 = (const uint32_t*)(g_wl + 3 * D_MODEL * D_MODEL);

    const int tid = threadIdx.x;
    const int w = tid >> 5;
    const int lane = tid & 31;
    const int g = lane >> 2;
    const int t = lane & 3;
    const int m0 = blockIdx.x * 64;
    const int n0 = blockIdx.y * 64;

    float acc[8][4] = {};

    for (int kb = 0; kb < 20; kb++) {
        __syncthreads();
        #pragma unroll
        for (int it = 0; it < 4; it++) {
            int idx = tid + it * 128;
            int r = idx >> 3, c = idx & 7;
            Ah[r * PA_STR + c] = xh32[(m0 + r) * DU32 + kb * 8 + c];
            Al[r * PA_STR + c] = xl32[(m0 + r) * DU32 + kb * 8 + c];
        }
        #pragma unroll
        for (int it = 0; it < 4; it++) {
            int idx = tid + it * 128;
            int r = idx >> 3, c = idx & 7;
            Wh[r * PA_STR + c] = wh32[(n0 + r) * DU32 + kb * 8 + c];
            Wl[r * PA_STR + c] = wl32[(n0 + r) * DU32 + kb * 8 + c];
        }
        __syncthreads();

        int r0 = (w * 16 + g) * PA_STR;
        int r1 = r0 + 8 * PA_STR;
        uint32_t ah0 = Ah[r0 + t], ah1 = Ah[r1 + t], ah2 = Ah[r0 + t + 4], ah3 = Ah[r1 + t + 4];
        uint32_t al0 = Al[r0 + t], al1 = Al[r1 + t], al2 = Al[r0 + t + 4], al3 = Al[r1 + t + 4];

        #pragma unroll
        for (int a = 0; a < 8; a++) {
            int br = (a * 8 + g) * PA_STR;
            uint32_t bh0 = Wh[br + t], bh1 = Wh[br + t + 4];
            uint32_t bl0 = Wl[br + t], bl1 = Wl[br + t + 4];
            mma_f16(acc[a], ah0, ah1, ah2, ah3, bh0, bh1);
            mma_f16(acc[a], al0, al1, al2, al3, bh0, bh1);
            mma_f16(acc[a], ah0, ah1, ah2, ah3, bl0, bl1);
        }
    }

    int row = m0 + w * 16 + g;
    #pragma unroll
    for (int a = 0; a < 8; a++) {
        int col = n0 + 8 * a + 2 * t;
        float b0v = bo[col], b1v = bo[col + 1];
        float2 v0 = make_float2(acc[a][0] + b0v, acc[a][1] + b1v);
        float2 v1 = make_float2(acc[a][2] + b0v, acc[a][3] + b1v);
        *(float2*)&out[row * D_MODEL + col] = v0;
        *(float2*)&out[(row + 8) * D_MODEL + col] = v1;
    }
}

// ============================================================
// Flash attention, split-K x2. CTA = 64 q x 1 head x 2048 keys.
// Fixed-base exp2 softmax, register P, l via ones-column.
// Emits unnormalized fp32 O partial + l partial.
// ============================================================
#define QS_STRIDE 28
#define KS_STRIDE 28
#define VS_STRIDE 28
#define KV_TILE (64 * 28)
#define KV_TILE_B (KV_TILE * 4)

__global__ void __launch_bounds__(128) attn_kernel()
{
    __shared__ __align__(16) uint32_t Qs[64 * QS_STRIDE];
    __shared__ __align__(16) uint32_t Ks[2 * KV_TILE];
    __shared__ __align__(16) uint32_t Vs[2 * KV_TILE];

    const uint32_t* __restrict__ q32 = (const uint32_t*)g_qh;
    const uint32_t* __restrict__ k32 = (const uint32_t*)g_kh;
    const uint32_t* __restrict__ v32 = (const uint32_t*)g_vh;

    const int tid = threadIdx.x;
    const int w = tid >> 5;
    const int lane = tid & 31;
    const int g = lane >> 2;
    const int t = lane & 3;
    const int head = blockIdx.y;
    const int split = blockIdx.z;
    const int q0 = blockIdx.x * BR;
    const int hoff = head * (DH / 2);
    const int kb0 = split * KRANGE;

    const uint32_t ks_sh = (uint32_t)__cvta_generic_to_shared(&Ks[0]);
    const uint32_t vs_sh = (uint32_t)__cvta_generic_to_shared(&Vs[0]);

    // ---- prologue: K pad cols zero; V col 20 = ones, 21..23 zero ----
    for (int idx = tid; idx < 2 * 64 * 4; idx += 128) {
        int st = idx >> 8;
        int rem = idx & 255;
        int r = rem >> 2, c = 20 + (rem & 3);
        Ks[st * KV_TILE + r * KS_STRIDE + c] = 0u;
        Vs[st * KV_TILE + r * VS_STRIDE + c] = (c == 20) ? 0x3C003C00u : 0u;
    }

    // ---- load Q tile ----
    for (int idx = tid; idx < 64 * 24; idx += 128) {
        int r = idx / 24, c = idx % 24;
        Qs[r * QS_STRIDE + c] = (c < 20) ? q32[(q0 + r) * DU32 + hoff + c] : 0u;
    }

    // ---- hoisted cp.async addressing ----
    const uint32_t* srcPtr[5];
    uint32_t dstOff[5];
    #pragma unroll
    for (int j = 0; j < 5; j++) {
        int idx = tid + j * 128;
        int i2 = idx;
        bool isV = i2 >= 320;
        if (isV) i2 -= 320;
        int r = i2 / 5, c = i2 % 5;
        srcPtr[j] = (isV ? v32 : k32) + (kb0 + r) * DU32 + hoff + c * 4;
        dstOff[j] = (isV ? vs_sh : ks_sh) + (r * KS_STRIDE + c * 4) * 4;
    }

    #pragma unroll
    for (int j = 0; j < 5; j++) {
        CP_ASYNC16(dstOff[j], srcPtr[j]);
        srcPtr[j] += BC * DU32;
    }
    CP_COMMIT();
    __syncthreads();

    // ---- Q A-fragments register-resident ----
    uint32_t qa[3][4];
    {
        int r0 = (w * 16 + g) * QS_STRIDE;
        int r1 = r0 + 8 * QS_STRIDE;
        #pragma unroll
        for (int ks = 0; ks < 3; ks++) {
            qa[ks][0] = Qs[r0 + ks * 8 + t];
            qa[ks][1] = Qs[r1 + ks * 8 + t];
            qa[ks][2] = Qs[r0 + ks * 8 + t + 4];
            qa[ks][3] = Qs[r1 + ks * 8 + t + 4];
        }
    }

    float o[6][4] = {};

    const int NIT = KRANGE / BC;
    for (int iter = 0; iter < NIT; iter++) {
        const int st = iter & 1;

        if (iter + 1 < NIT) {
            const uint32_t so = ((iter + 1) & 1) * KV_TILE_B;
            #pragma unroll
            for (int j = 0; j < 5; j++) {
                CP_ASYNC16(dstOff[j] + so, srcPtr[j]);
                srcPtr[j] += BC * DU32;
            }
            CP_COMMIT();
            CP_WAIT1();
        } else {
            CP_WAIT0();
        }
        __syncthreads();

        const uint32_t* Kst = &Ks[st * KV_TILE];
        const uint32_t vrow = vs_sh + st * KV_TILE_B + (lane & 15) * (VS_STRIDE * 4);

        // ---- S = Q K^T (log2 domain) ----
        float s[8][4];
        #pragma unroll
        for (int a = 0; a < 8; a++)
            #pragma unroll
            for (int j = 0; j < 4; j++) s[a][j] = 0.f;

        #pragma unroll
        for (int ks = 0; ks < 3; ks++) {
            #pragma unroll
            for (int a = 0; a < 8; a++) {
                int kr = (a * 8 + g) * KS_STRIDE + ks * 8 + t;
                mma_f16(s[a], qa[ks][0], qa[ks][1], qa[ks][2], qa[ks][3],
                        Kst[kr], Kst[kr + 4]);
            }
        }

        // ---- P = 2^S into PV A-fragments ----
        uint32_t p01[8], p23[8];
        #pragma unroll
        for (int a = 0; a < 8; a++) {
            p01[a] = exp2_f16x2(s[a][0], s[a][1]);
            p23[a] = exp2_f16x2(s[a][2], s[a][3]);
        }

        // ---- O += P @ [V | 1] ----
        #pragma unroll
        for (int ks = 0; ks < 4; ks++) {
            uint32_t vk = vrow + ks * (16 * VS_STRIDE * 4);
            #pragma unroll
            for (int n = 0; n < 6; n++) {
                uint32_t b0, b1;
                ldmatrix_x2_trans(b0, b1, vk + n * 16);
                mma_f16(o[n], p01[2 * ks], p23[2 * ks],
                        p01[2 * ks + 1], p23[2 * ks + 1], b0, b1);
            }
        }
        __syncthreads();
    }

    // ---- epilogue: store unnormalized partials ----
    int r0 = q0 + w * 16 + g;
    float* po = &g_po[split][0];
    #pragma unroll
    for (int n = 0; n < 5; n++) {
        int col = head * DH + n * 8 + 2 * t;
        *(float2*)&po[r0 * D_MODEL + col] = make_float2(o[n][0], o[n][1]);
        *(float2*)&po[(r0 + 8) * D_MODEL + col] = make_float2(o[n][2], o[n][3]);
    }
    if (t == 0) {
        g_pl[split][head * S_LEN + r0] = o[5][0];
        g_pl[split][head * S_LEN + r0 + 8] = o[5][2];
    }
}

// ============================================================
// Combine: ctx = (O0 + O1) / (l0 + l1) -> (hi,lo) fp16 split
// ============================================================
__global__ void __launch_bounds__(256) attn_combine()
{
    int i = blockIdx.x * 256 + threadIdx.x;   // u32 index over [S_LEN][DU32]
    if (i >= S_LEN * DU32) return;
    int row = i / DU32;
    int cu = i % DU32;
    int head = cu / (DH / 2);

    float l = g_pl[0][head * S_LEN + row] + g_pl[1][head * S_LEN + row];
    float inv = 1.f / l;
    float2 a = *(const float2*)&g_po[0][i * 2];
    float2 b = *(const float2*)&g_po[1][i * 2];
    float v0 = (a.x + b.x) * inv;
    float v1 = (a.y + b.y) * inv;

    __half2 h = __floats2half2_rn(v0, v1);
    __half2 e = __floats2half2_rn(v0 - __half2float(__low2half(h)),
                                  v1 - __half2float(__high2half(h)));
    ((uint32_t*)g_ch)[i] = *(uint32_t*)&h;
    ((uint32_t*)g_cl)[i] = *(uint32_t*)&e;
}

// ============================================================
extern "C" void kernel_launch(void* const* d_in, const int* in_sizes, int n_in,
                              void* d_out, int out_size)
{
    const float* x  = (const float*)d_in[0];
    const float* Wq = (const float*)d_in[1];
    const float* Wk = (const float*)d_in[2];
    const float* Wv = (const float*)d_in[3];
    const float* Wo = (const float*)d_in[4];
    const float* bo = (const float*)d_in[5];
    float* out = (float*)d_out;

    convert_x_kernel<<<(S_LEN * D_MODEL + 255) / 256, 256>>>(x);
    convert_w_kernel<<<dim3((D_MODEL * D_MODEL + 255) / 256, 1, 4), 256>>>(Wq, Wk, Wv, Wo);

    gemm_qkv_h<<<dim3(S_LEN / 128, D_MODEL / 64, 3), 256>>>();
    attn_kernel<<<dim3(S_LEN / BR, NH, NSPLIT), 128>>>();
    attn_combine<<<(S_LEN * DU32 + 255) / 256, 256>>>();
    gemm_out_h<<<dim3(S_LEN / 64, D_MODEL / 64), 128>>>(bo, out);
}